// round 4
// baseline (speedup 1.0000x reference)
#include <cuda_runtime.h>
#include <math.h>

// ---------------------------------------------------------------------------
// HierarchicalCNN: two 3-layer strided conv1d nets + pooled heads + routing.
//
//   x    : [512, 2, 4096]
//   a1   : [512, 128, 1024]  (conv1 out, scratch, reused per net)
//   feat : [2][512][256]     (pooled sums; /512 in head)
//   out  : [512, 4]
//
// conv0 (2->64) fused into conv1. Mainloops use packed fma.rn.f32x2 with
// accumulators paired along t. Activations are stored parity-split in smem
// (even/odd input positions) so b-pairs are direct LDS.64; weights are
// stored duplicated ({w,w}) so a-pairs are direct LDS.128. No packs on the
// hot path except taps k=2,3.
//
// SAME padding, stride 2, K=5: pad_lo = 1 -> input index = 2*t + k - 1.
// Tap->parity map (t local, pair {t,t+1}, pi = local pair base):
//   k=0: {odd[pi],  odd[pi+1]}   k=1: {even[pi], even[pi+1]}
//   k=2: {odd[pi+1],odd[pi+2]}   k=3: {even[pi+1],even[pi+2]}
//   k=4: {odd[pi+2],odd[pi+3]}
// smem build: window col c (input pos q=2*tt0-1+c): c even -> odd[c/2],
//             c odd -> even[(c-1)/2].
// ---------------------------------------------------------------------------

__device__ float g_a1[(size_t)512 * 128 * 1024];
__device__ float g_feat[2][512][256];

typedef unsigned long long ull;

__device__ __forceinline__ void fma2(ull& d, ull a, ull b) {
    asm("fma.rn.f32x2 %0, %1, %2, %0;" : "+l"(d) : "l"(a), "l"(b));
}
__device__ __forceinline__ ull pack2(float lo, float hi) {
    ull r;
    asm("mov.b64 %0, {%1, %2};" : "=l"(r) : "f"(lo), "f"(hi));
    return r;
}
__device__ __forceinline__ void unpack2(ull v, float& lo, float& hi) {
    asm("mov.b64 {%0, %1}, %2;" : "=f"(lo), "=f"(hi) : "l"(v));
}

#define WP 260   // wsd pitch (floats): %4==0 keeps LDS.128 16B-aligned
#define XP 132   // parity-array pitch (needs >=130)

// ---------------------------------------------------------------------------
// conv01: x[B,2,4096] -> (conv0+relu recomputed per tile) -> conv1+relu
//         -> a1[B,128,1024]
// CTA: (sample b, 128-wide t tile). 256 thr. Thread: co = ty*8+cj (ty=tid>>4),
// t pairs {pi, pi+1}, pi = 2*tx + 32*jj (tx=tid&15, jj=0..3).
// K streamed in ci chunks of 4.
// ---------------------------------------------------------------------------
__global__ __launch_bounds__(256, 2)
void conv01_kernel(const float* __restrict__ x,
                   const float* __restrict__ w0,  // [64,2,5]
                   const float* __restrict__ b0,  // [64]
                   const float* __restrict__ w1,  // [128,64,5]
                   const float* __restrict__ b1,  // [128]
                   float* __restrict__ out)       // [512,128,1024]
{
    const int b   = blockIdx.x;
    const int tt0 = blockIdx.y * 128;
    const int tid = threadIdx.x;
    const int tx  = tid & 15;
    const int ty  = tid >> 4;

    const int tmid0 = 2 * tt0 - 1;       // layer-0 t window start (260 wide)
    const int x0    = 2 * tmid0 - 1;     // x window start (523 wide)

    __shared__ float xs0[2][524];
    __shared__ float w0s[64 * 10];
    __shared__ float b0s[64];
    __shared__ float wsd[20][WP];        // conv1 W, duplicated: [kk][2co]=[2co+1]
    __shared__ float xse[4][XP];         // layer-0 act, even input positions
    __shared__ float xso[4][XP];         // layer-0 act, odd input positions

    for (int i = tid; i < 640; i += 256) w0s[i] = w0[i];
    if (tid < 64) b0s[tid] = b0[tid];

    const float* xb = x + (size_t)b * 2 * 4096;
    for (int i = tid; i < 2 * 524; i += 256) {
        int row = i / 524, col = i % 524;
        int gx = x0 + col;
        xs0[row][col] = (gx >= 0 && gx < 4096) ? xb[(size_t)row * 4096 + gx] : 0.0f;
    }

    ull acc2[8][4];
#pragma unroll
    for (int i = 0; i < 8; i++)
#pragma unroll
        for (int j = 0; j < 4; j++) acc2[i][j] = 0ull;

    __syncthreads();

    for (int ci0 = 0; ci0 < 64; ci0 += 4) {
        // W tile: 128 co x 20 (ci,k) entries, stored duplicated. 10/thread.
#pragma unroll
        for (int r = 0; r < 10; r++) {
            int flat = r * 256 + tid;
            int co = flat / 20;
            int kk = flat % 20;
            float wv = w1[(size_t)co * (64 * 5) + ci0 * 5 + kk];
            *reinterpret_cast<float2*>(&wsd[kk][2 * co]) = make_float2(wv, wv);
        }
        // layer-0 activations for this ci chunk, parity-split. 4 x 260 window.
        for (int i = tid; i < 4 * 260; i += 256) {
            int row = i / 260, col = i % 260;
            int ci = ci0 + row;
            int tmid = tmid0 + col;
            float v = 0.0f;
            if (tmid >= 0 && tmid < 2048) {
                float a = b0s[ci];
                const float* wc = &w0s[ci * 10];
#pragma unroll
                for (int k = 0; k < 5; k++) a = fmaf(wc[k],     xs0[0][2 * col + k], a);
#pragma unroll
                for (int k = 0; k < 5; k++) a = fmaf(wc[5 + k], xs0[1][2 * col + k], a);
                v = fmaxf(a, 0.0f);
            }
            if (col & 1) xse[row][(col - 1) >> 1] = v;
            else         xso[row][col >> 1] = v;
        }
        __syncthreads();

#pragma unroll
        for (int ci = 0; ci < 4; ci++) {
#pragma unroll
            for (int k = 0; k < 5; k++) {
                const ull* wr = reinterpret_cast<const ull*>(&wsd[ci * 5 + k][0]) + ty * 8;
                ull a2[8];
#pragma unroll
                for (int c = 0; c < 8; c++) a2[c] = wr[c];
#pragma unroll
                for (int jj = 0; jj < 4; jj++) {
                    int pi = 2 * tx + 32 * jj;
                    ull bb;
                    if (k == 0)      bb = *reinterpret_cast<const ull*>(&xso[ci][pi]);
                    else if (k == 1) bb = *reinterpret_cast<const ull*>(&xse[ci][pi]);
                    else if (k == 2) bb = pack2(xso[ci][pi + 1], xso[ci][pi + 2]);
                    else if (k == 3) bb = pack2(xse[ci][pi + 1], xse[ci][pi + 2]);
                    else             bb = *reinterpret_cast<const ull*>(&xso[ci][pi + 2]);
#pragma unroll
                    for (int c = 0; c < 8; c++) fma2(acc2[c][jj], a2[c], bb);
                }
            }
        }
        __syncthreads();
    }

#pragma unroll
    for (int cj = 0; cj < 8; cj++) {
        int co = ty * 8 + cj;
        float bv = b1[co];
        float* ob = out + ((size_t)b * 128 + co) * 1024 + tt0;
#pragma unroll
        for (int jj = 0; jj < 4; jj++) {
            float lo, hi;
            unpack2(acc2[cj][jj], lo, hi);
            *reinterpret_cast<float2*>(&ob[2 * tx + 32 * jj]) =
                make_float2(fmaxf(lo + bv, 0.0f), fmaxf(hi + bv, 0.0f));
        }
    }
}

// ---------------------------------------------------------------------------
// conv2: a1[B,128,1024] -> conv+relu -> fused mean-pool into feat sums.
// Same scheme; input read from gmem instead of recomputed.
// ---------------------------------------------------------------------------
__global__ __launch_bounds__(256, 2)
void conv2_kernel(const float* __restrict__ in,    // [B,128,1024]
                  const float* __restrict__ w,     // [256,128,5]
                  const float* __restrict__ bias,  // [256]
                  float* __restrict__ feat)        // [B,256] sums
{
    const int b   = blockIdx.x;
    const int tt0 = blockIdx.y * 128;
    const int co0 = blockIdx.z * 128;
    const int tid = threadIdx.x;
    const int tx  = tid & 15;
    const int ty  = tid >> 4;

    __shared__ float wsd[20][WP];
    __shared__ float xse[4][XP];
    __shared__ float xso[4][XP];

    ull acc2[8][4];
#pragma unroll
    for (int i = 0; i < 8; i++)
#pragma unroll
        for (int j = 0; j < 4; j++) acc2[i][j] = 0ull;

    const float* inb = in + (size_t)b * 128 * 1024;

    for (int ci0 = 0; ci0 < 128; ci0 += 4) {
#pragma unroll
        for (int r = 0; r < 10; r++) {
            int flat = r * 256 + tid;
            int co = flat / 20;
            int kk = flat % 20;
            float wv = w[(size_t)(co0 + co) * (128 * 5) + ci0 * 5 + kk];
            *reinterpret_cast<float2*>(&wsd[kk][2 * co]) = make_float2(wv, wv);
        }
        for (int i = tid; i < 4 * 260; i += 256) {
            int row = i / 260, col = i % 260;
            int gt = 2 * tt0 - 1 + col;
            float v = (gt >= 0 && gt < 1024)
                          ? inb[(size_t)(ci0 + row) * 1024 + gt] : 0.0f;
            if (col & 1) xse[row][(col - 1) >> 1] = v;
            else         xso[row][col >> 1] = v;
        }
        __syncthreads();

#pragma unroll
        for (int ci = 0; ci < 4; ci++) {
#pragma unroll
            for (int k = 0; k < 5; k++) {
                const ull* wr = reinterpret_cast<const ull*>(&wsd[ci * 5 + k][0]) + ty * 8;
                ull a2[8];
#pragma unroll
                for (int c = 0; c < 8; c++) a2[c] = wr[c];
#pragma unroll
                for (int jj = 0; jj < 4; jj++) {
                    int pi = 2 * tx + 32 * jj;
                    ull bb;
                    if (k == 0)      bb = *reinterpret_cast<const ull*>(&xso[ci][pi]);
                    else if (k == 1) bb = *reinterpret_cast<const ull*>(&xse[ci][pi]);
                    else if (k == 2) bb = pack2(xso[ci][pi + 1], xso[ci][pi + 2]);
                    else if (k == 3) bb = pack2(xse[ci][pi + 1], xse[ci][pi + 2]);
                    else             bb = *reinterpret_cast<const ull*>(&xso[ci][pi + 2]);
#pragma unroll
                    for (int c = 0; c < 8; c++) fma2(acc2[c][jj], a2[c], bb);
                }
            }
        }
        __syncthreads();
    }

    // fused mean-pool: relu, sum both halves of each t-pair, reduce 16 tx
    // lanes (xor 8/4/2/1 stays within each 16-lane half-warp), atomicAdd.
    float* fb = feat + (size_t)b * 256;
#pragma unroll
    for (int cj = 0; cj < 8; cj++) {
        int co = co0 + ty * 8 + cj;
        float bv = bias[co];
        float s = 0.0f;
#pragma unroll
        for (int jj = 0; jj < 4; jj++) {
            float lo, hi;
            unpack2(acc2[cj][jj], lo, hi);
            s += fmaxf(lo + bv, 0.0f) + fmaxf(hi + bv, 0.0f);
        }
#pragma unroll
        for (int off = 8; off > 0; off >>= 1)
            s += __shfl_xor_sync(0xffffffffu, s, off);
        if (tx == 0) atomicAdd(&fb[co], s);
    }
}

// ---------------------------------------------------------------------------
__global__ void zero_feat_kernel()
{
    int i = blockIdx.x * 256 + threadIdx.x;
    if (i < 2 * 512 * 256) ((float*)g_feat)[i] = 0.0f;
}

// ---------------------------------------------------------------------------
// heads + softmax + hierarchical routing. 1 warp per sample.
// ---------------------------------------------------------------------------
__global__ __launch_bounds__(32)
void head_kernel(const float* __restrict__ wh1, const float* __restrict__ bh1,
                 const float* __restrict__ wh2, const float* __restrict__ bh2,
                 float* __restrict__ out)
{
    const int b = blockIdx.x;
    const int lane = threadIdx.x;
    const float* f1 = &g_feat[0][b][0];
    const float* f2 = &g_feat[1][b][0];
    const float inv_pool = 1.0f / 512.0f;

    float lg1[3], lg2[2];
#pragma unroll
    for (int cls = 0; cls < 3; cls++) {
        float s = 0.0f;
        for (int c = lane; c < 256; c += 32) s += f1[c] * wh1[cls * 256 + c];
#pragma unroll
        for (int off = 16; off > 0; off >>= 1) s += __shfl_xor_sync(0xffffffffu, s, off);
        lg1[cls] = s * inv_pool + bh1[cls];
    }
#pragma unroll
    for (int cls = 0; cls < 2; cls++) {
        float s = 0.0f;
        for (int c = lane; c < 256; c += 32) s += f2[c] * wh2[cls * 256 + c];
#pragma unroll
        for (int off = 16; off > 0; off >>= 1) s += __shfl_xor_sync(0xffffffffu, s, off);
        lg2[cls] = s * inv_pool + bh2[cls];
    }

    if (lane == 0) {
        float m = fmaxf(lg1[0], fmaxf(lg1[1], lg1[2]));
        float e0 = expf(lg1[0] - m), e1 = expf(lg1[1] - m), e2 = expf(lg1[2] - m);
        float inv = 1.0f / (e0 + e1 + e2);
        float p0 = e0 * inv, p1 = e1 * inv, p2 = e2 * inv;
        int pred = 0; float best = p0;
        if (p1 > best) { best = p1; pred = 1; }
        if (p2 > best) { best = p2; pred = 2; }

        float m2 = fmaxf(lg2[0], lg2[1]);
        float q0 = expf(lg2[0] - m2), q1 = expf(lg2[1] - m2);
        float inv2 = 1.0f / (q0 + q1);
        q0 *= inv2; q1 *= inv2;

        out[b * 4 + 0] = (pred == 0) ? p0 : 0.0f;
        out[b * 4 + 1] = (pred == 1) ? p1 : 0.0f;
        out[b * 4 + 2] = (pred == 2) ? q0 : 0.0f;
        out[b * 4 + 3] = (pred == 2) ? q1 : 0.0f;
    }
}

// ---------------------------------------------------------------------------
extern "C" void kernel_launch(void* const* d_in, const int* in_sizes, int n_in,
                              void* d_out, int out_size)
{
    (void)in_sizes; (void)n_in; (void)out_size;
    const float* x = (const float*)d_in[0];

    const float* W[2][8];
    for (int net = 0; net < 2; net++)
        for (int i = 0; i < 8; i++)
            W[net][i] = (const float*)d_in[1 + net * 8 + i];

    float* out = (float*)d_out;

    float *a1, *feat;
    cudaGetSymbolAddress((void**)&a1, g_a1);
    cudaGetSymbolAddress((void**)&feat, g_feat);

    zero_feat_kernel<<<1024, 256>>>();

    for (int net = 0; net < 2; net++) {
        conv01_kernel<<<dim3(512, 8), 256>>>(x, W[net][0], W[net][1],
                                             W[net][2], W[net][3], a1);
        conv2_kernel<<<dim3(512, 4, 2), 256>>>(a1, W[net][4], W[net][5],
                                               feat + (size_t)net * 512 * 256);
    }

    head_kernel<<<512, 32>>>(W[0][6], W[0][7], W[1][6], W[1][7], out);
}

// round 6
// speedup vs baseline: 1.1890x; 1.1890x over previous
#include <cuda_runtime.h>
#include <cuda_bf16.h>
#include <math.h>

// ---------------------------------------------------------------------------
// HierarchicalCNN: two 3-layer strided conv1d nets + pooled heads + routing.
//
//   x    : [512, 2, 4096]
//   a1   : [512, 128, 1024]  (conv1 out fp32, scratch, reused per net)
//   feat : [2][512][256]     (pooled sums; /512 in head)
//   out  : [512, 4]
//
// conv0+conv1 fused (fma.rn.f32x2 path, proven R3 code).
// conv2 on warp-level tensor cores (mma.sync m16n8k16 bf16, baseline PTX —
// tcgen05 unavailable: harness compiles compute_100, not 100a), with bf16
// hi/lo 3-pass split (hh+hl+lh, error ~1e-5):
//   D[co,t] = sum over (ci, tap) of W[co,ci,tap] * a1[ci, 2t+tap-1]
// K streamed as 8 ci-chunks of 16 x 5 taps. Pool fused into epilogue.
// ---------------------------------------------------------------------------

typedef unsigned int       u32;
typedef unsigned long long ull;

__device__ float g_a1[(size_t)512 * 128 * 1024];
__device__ float g_feat[2][512][256];

// ---------------- packed fp32x2 helpers (conv01 path) ----------------------
__device__ __forceinline__ void fma2(ull& d, ull a, ull b) {
    asm("fma.rn.f32x2 %0, %1, %2, %0;" : "+l"(d) : "l"(a), "l"(b));
}
__device__ __forceinline__ ull pack2(float lo, float hi) {
    ull r;
    asm("mov.b64 %0, {%1, %2};" : "=l"(r) : "f"(lo), "f"(hi));
    return r;
}
__device__ __forceinline__ void unpack2(ull v, float& lo, float& hi) {
    asm("mov.b64 {%0, %1}, %2;" : "=f"(lo), "=f"(hi) : "l"(v));
}

// ---------------- warp-MMA helpers -----------------------------------------
__device__ __forceinline__ u32 smem_u32(const void* p) {
    u32 a;
    asm("{ .reg .u64 t; cvta.to.shared.u64 t, %1; cvt.u32.u64 %0, t; }"
        : "=r"(a) : "l"(p));
    return a;
}
__device__ __forceinline__ void ldsm4(u32 addr, u32* r) {
    asm volatile("ldmatrix.sync.aligned.m8n8.x4.shared.b16 {%0,%1,%2,%3}, [%4];"
                 : "=r"(r[0]), "=r"(r[1]), "=r"(r[2]), "=r"(r[3]) : "r"(addr));
}
__device__ __forceinline__ void ldsm2(u32 addr, u32* r) {
    asm volatile("ldmatrix.sync.aligned.m8n8.x2.shared.b16 {%0,%1}, [%2];"
                 : "=r"(r[0]), "=r"(r[1]) : "r"(addr));
}
__device__ __forceinline__ void mma_bf16(float* d, const u32* a, const u32* b) {
    asm volatile(
        "mma.sync.aligned.m16n8k16.row.col.f32.bf16.bf16.f32 "
        "{%0,%1,%2,%3}, {%4,%5,%6,%7}, {%8,%9}, {%0,%1,%2,%3};"
        : "+f"(d[0]), "+f"(d[1]), "+f"(d[2]), "+f"(d[3])
        : "r"(a[0]), "r"(a[1]), "r"(a[2]), "r"(a[3]), "r"(b[0]), "r"(b[1]));
}

#define WPITCH 132

// ---------------------------------------------------------------------------
// conv01 (proven R3 fma2 path, unchanged)
// ---------------------------------------------------------------------------
__global__ __launch_bounds__(256, 2)
void conv01_kernel(const float* __restrict__ x,
                   const float* __restrict__ w0,  // [64,2,5]
                   const float* __restrict__ b0,  // [64]
                   const float* __restrict__ w1,  // [128,64,5]
                   const float* __restrict__ b1,  // [128]
                   float* __restrict__ out)       // [512,128,1024]
{
    const int b   = blockIdx.x;
    const int tt0 = blockIdx.y * 128;
    const int tid = threadIdx.x;
    const int tx  = tid & 15;
    const int ty  = tid >> 4;

    const int tmid0 = 2 * tt0 - 1;
    const int x0    = 2 * tmid0 - 1;

    __shared__ float xs0[2][524];
    __shared__ float w0s[64 * 10];
    __shared__ float b0s[64];
    __shared__ float ws[40][WPITCH];
    __shared__ float xs[8][260];

    for (int i = tid; i < 640; i += 256) w0s[i] = w0[i];
    if (tid < 64) b0s[tid] = b0[tid];

    const float* xb = x + (size_t)b * 2 * 4096;
    for (int i = tid; i < 2 * 524; i += 256) {
        int row = i / 524, col = i % 524;
        int gx = x0 + col;
        xs0[row][col] = (gx >= 0 && gx < 4096) ? xb[(size_t)row * 4096 + gx] : 0.0f;
    }

    ull acc2[4][8];
#pragma unroll
    for (int i = 0; i < 4; i++)
#pragma unroll
        for (int j = 0; j < 8; j++) acc2[i][j] = 0ull;

    __syncthreads();

    for (int ci0 = 0; ci0 < 64; ci0 += 8) {
#pragma unroll
        for (int r = 0; r < 20; r++) {
            int flat = r * 256 + tid;
            int co = flat / 40;
            int kk = flat % 40;
            ws[kk][co] = w1[(size_t)co * (64 * 5) + ci0 * 5 + kk];
        }
        for (int i = tid; i < 8 * 260; i += 256) {
            int row = i / 260, col = i % 260;
            int ci = ci0 + row;
            int tmid = tmid0 + col;
            float v = 0.0f;
            if (tmid >= 0 && tmid < 2048) {
                float a = b0s[ci];
                const float* wc = &w0s[ci * 10];
#pragma unroll
                for (int k = 0; k < 5; k++) a = fmaf(wc[k],     xs0[0][2 * col + k], a);
#pragma unroll
                for (int k = 0; k < 5; k++) a = fmaf(wc[5 + k], xs0[1][2 * col + k], a);
                v = fmaxf(a, 0.0f);
            }
            xs[row][col] = v;
        }
        __syncthreads();

#pragma unroll
        for (int ci = 0; ci < 8; ci++) {
#pragma unroll
            for (int k = 0; k < 5; k++) {
                const float4* wr =
                    reinterpret_cast<const float4*>(&ws[ci * 5 + k][ty * 8]);
                float4 al = wr[0], ah = wr[1];
                ull a2[4];
                a2[0] = pack2(al.x, al.y);
                a2[1] = pack2(al.z, al.w);
                a2[2] = pack2(ah.x, ah.y);
                a2[3] = pack2(ah.z, ah.w);
                ull b2[8];
#pragma unroll
                for (int j = 0; j < 8; j++) {
                    float bv = xs[ci][2 * (tx + 16 * j) + k];
                    b2[j] = pack2(bv, bv);
                }
#pragma unroll
                for (int cp = 0; cp < 4; cp++)
#pragma unroll
                    for (int tj = 0; tj < 8; tj++)
                        fma2(acc2[cp][tj], a2[cp], b2[tj]);
            }
        }
        __syncthreads();
    }

#pragma unroll
    for (int cp = 0; cp < 4; cp++) {
        int co_lo = ty * 8 + 2 * cp;
        float bl = b1[co_lo], bh = b1[co_lo + 1];
        float* ol = out + ((size_t)b * 128 + co_lo) * 1024 + tt0;
        float* oh = ol + 1024;
#pragma unroll
        for (int tj = 0; tj < 8; tj++) {
            float lo, hi;
            unpack2(acc2[cp][tj], lo, hi);
            int t = tx + 16 * tj;
            ol[t] = fmaxf(lo + bl, 0.0f);
            oh[t] = fmaxf(hi + bh, 0.0f);
        }
    }
}

// ---------------------------------------------------------------------------
// conv2 via warp-MMA bf16x3 + fused pool.
// grid (512 b, 4 t-tiles, 2 co-halves), 256 threads (8 warps).
// CTA tile 128co x 128t; warp tile 32co x 64t (warps: 4 co-groups x 2 t).
// smem tiles (dynamic):
//   raw fp32 [16 ci][260]               (halo window of a1)
//   A  bf16  [plane 2][tap 5][128co][24ci-pitch]  (weights hi/lo)
//   B  bf16  [plane 2][tap 5][128 t][24ci-pitch]  (im2col hi/lo)
// pitch 24 bf16 = 48 B: 16B-aligned, stride-48 ldmatrix rows conflict-free.
// ---------------------------------------------------------------------------
#define OFF_RAW 0
#define RAW_BYTES (16 * 260 * 4)                 // 16640
#define OFF_A   RAW_BYTES
#define TILE_BYTES (128 * 24 * 2)                // 6144 per (plane,tap)
#define A_BYTES (2 * 5 * TILE_BYTES)             // 61440
#define OFF_B   (OFF_A + A_BYTES)
#define C2_SMEM (OFF_B + A_BYTES)                // 139520

__global__ __launch_bounds__(256)
void conv2_mma_kernel(const float* __restrict__ in,    // [512,128,1024] fp32
                      const float* __restrict__ w,     // [256,128,5]
                      const float* __restrict__ bias,  // [256]
                      float* __restrict__ feat)        // [512,256] sums
{
    extern __shared__ char smem[];
    const u32 sb   = smem_u32(smem);
    const int tid  = threadIdx.x;
    const int wid  = tid >> 5;
    const int lane = tid & 31;
    const int b    = blockIdx.x;
    const int tt0  = blockIdx.y * 128;
    const int co0  = blockIdx.z * 128;

    const int wco = (wid & 3) * 32;   // warp co offset within tile
    const int wt  = (wid >> 2) * 64;  // warp t offset within tile

    float* raw = (float*)(smem + OFF_RAW);

    float acc[2][8][4];
#pragma unroll
    for (int m = 0; m < 2; m++)
#pragma unroll
        for (int j = 0; j < 8; j++)
#pragma unroll
            for (int e = 0; e < 4; e++) acc[m][j][e] = 0.0f;

    // per-lane ldmatrix row offsets (bytes)
    const u32 arow = (u32)((lane & 15) * 48 + (lane >> 4) * 16);
    const u32 brow = (u32)((lane & 7) * 48 + ((lane >> 3) & 1) * 16);

    const float* inb = in + (size_t)b * 128 * 1024;

    for (int ci0 = 0; ci0 < 128; ci0 += 16) {
        // raw fp32 window [16][260], zero-padded halo
        for (int i = tid; i < 16 * 260; i += 256) {
            int row = i / 260, col = i % 260;
            int g = 2 * tt0 - 1 + col;
            raw[i] = (g >= 0 && g < 1024)
                         ? inb[(size_t)(ci0 + row) * 1024 + g] : 0.0f;
        }
        // A stage: contiguous gmem block [128co][80(ci,tap)] -> hi/lo tiles
        for (int i = tid; i < 128 * 80; i += 256) {
            int r = i / 80, q = i % 80;
            int ci = q / 5, tap = q % 5;
            float v = w[(size_t)(co0 + r) * 640 + (size_t)ci0 * 5 + q];
            __nv_bfloat16 hi = __float2bfloat16(v);
            __nv_bfloat16 lo = __float2bfloat16(v - __bfloat162float(hi));
            char* base = smem + OFF_A + tap * TILE_BYTES + r * 48 + ci * 2;
            *(__nv_bfloat16*)base = hi;
            *(__nv_bfloat16*)(base + 5 * TILE_BYTES) = lo;
        }
        // B stage: im2col B[tap][t][ci] = raw[ci][2t+tap] -> hi/lo tiles
        for (int i = tid; i < 5 * 128 * 16; i += 256) {
            int tap = i / 2048;
            int rem = i % 2048;
            int t = rem / 16, ci = rem % 16;
            float v = raw[ci * 260 + 2 * t + tap];
            __nv_bfloat16 hi = __float2bfloat16(v);
            __nv_bfloat16 lo = __float2bfloat16(v - __bfloat162float(hi));
            char* base = smem + OFF_B + tap * TILE_BYTES + t * 48 + ci * 2;
            *(__nv_bfloat16*)base = hi;
            *(__nv_bfloat16*)(base + 5 * TILE_BYTES) = lo;
        }
        __syncthreads();

#pragma unroll
        for (int tap = 0; tap < 5; tap++) {
            const u32 aBaseH = sb + OFF_A + tap * TILE_BYTES;
            const u32 bBaseH = sb + OFF_B + tap * TILE_BYTES;
            u32 ah[2][4], al[2][4];
#pragma unroll
            for (int m = 0; m < 2; m++) {
                u32 ra = aBaseH + (u32)((wco + m * 16) * 48) + arow;
                ldsm4(ra, ah[m]);
                ldsm4(ra + 5 * TILE_BYTES, al[m]);
            }
#pragma unroll
            for (int j = 0; j < 8; j++) {
                u32 rb = bBaseH + (u32)((wt + j * 8) * 48) + brow;
                u32 bh[2], bl[2];
                ldsm2(rb, bh);
                ldsm2(rb + 5 * TILE_BYTES, bl);
#pragma unroll
                for (int m = 0; m < 2; m++) {
                    mma_bf16(acc[m][j], ah[m], bh);
                    mma_bf16(acc[m][j], ah[m], bl);
                    mma_bf16(acc[m][j], al[m], bh);
                }
            }
        }
        __syncthreads();
    }

    // epilogue: D fragment (m16n8): thread holds rows r, r+8 (r=lane/4),
    // cols 2c, 2c+1 (c=lane%4). bias+relu per element, sum over t, quad
    // reduce, atomicAdd into per-sample feature sums.
    float* fb = feat + (size_t)b * 256;
#pragma unroll
    for (int m = 0; m < 2; m++) {
        int r0 = co0 + wco + m * 16 + (lane >> 2);
        int r1 = r0 + 8;
        float bv0 = __ldg(&bias[r0]);
        float bv1 = __ldg(&bias[r1]);
        float s0 = 0.0f, s1 = 0.0f;
#pragma unroll
        for (int j = 0; j < 8; j++) {
            s0 += fmaxf(acc[m][j][0] + bv0, 0.0f) + fmaxf(acc[m][j][1] + bv0, 0.0f);
            s1 += fmaxf(acc[m][j][2] + bv1, 0.0f) + fmaxf(acc[m][j][3] + bv1, 0.0f);
        }
        s0 += __shfl_xor_sync(0xffffffffu, s0, 1);
        s0 += __shfl_xor_sync(0xffffffffu, s0, 2);
        s1 += __shfl_xor_sync(0xffffffffu, s1, 1);
        s1 += __shfl_xor_sync(0xffffffffu, s1, 2);
        if ((lane & 3) == 0) {
            atomicAdd(&fb[r0], s0);
            atomicAdd(&fb[r1], s1);
        }
    }
}

// ---------------------------------------------------------------------------
__global__ void zero_feat_kernel()
{
    int i = blockIdx.x * 256 + threadIdx.x;
    if (i < 2 * 512 * 256) ((float*)g_feat)[i] = 0.0f;
}

// ---------------------------------------------------------------------------
// heads + softmax + hierarchical routing. 1 warp per sample.
// ---------------------------------------------------------------------------
__global__ __launch_bounds__(32)
void head_kernel(const float* __restrict__ wh1, const float* __restrict__ bh1,
                 const float* __restrict__ wh2, const float* __restrict__ bh2,
                 float* __restrict__ out)
{
    const int b = blockIdx.x;
    const int lane = threadIdx.x;
    const float* f1 = &g_feat[0][b][0];
    const float* f2 = &g_feat[1][b][0];
    const float inv_pool = 1.0f / 512.0f;

    float lg1[3], lg2[2];
#pragma unroll
    for (int cls = 0; cls < 3; cls++) {
        float s = 0.0f;
        for (int c = lane; c < 256; c += 32) s += f1[c] * wh1[cls * 256 + c];
#pragma unroll
        for (int off = 16; off > 0; off >>= 1) s += __shfl_xor_sync(0xffffffffu, s, off);
        lg1[cls] = s * inv_pool + bh1[cls];
    }
#pragma unroll
    for (int cls = 0; cls < 2; cls++) {
        float s = 0.0f;
        for (int c = lane; c < 256; c += 32) s += f2[c] * wh2[cls * 256 + c];
#pragma unroll
        for (int off = 16; off > 0; off >>= 1) s += __shfl_xor_sync(0xffffffffu, s, off);
        lg2[cls] = s * inv_pool + bh2[cls];
    }

    if (lane == 0) {
        float m = fmaxf(lg1[0], fmaxf(lg1[1], lg1[2]));
        float e0 = expf(lg1[0] - m), e1 = expf(lg1[1] - m), e2 = expf(lg1[2] - m);
        float inv = 1.0f / (e0 + e1 + e2);
        float p0 = e0 * inv, p1 = e1 * inv, p2 = e2 * inv;
        int pred = 0; float best = p0;
        if (p1 > best) { best = p1; pred = 1; }
        if (p2 > best) { best = p2; pred = 2; }

        float m2 = fmaxf(lg2[0], lg2[1]);
        float q0 = expf(lg2[0] - m2), q1 = expf(lg2[1] - m2);
        float inv2 = 1.0f / (q0 + q1);
        q0 *= inv2; q1 *= inv2;

        out[b * 4 + 0] = (pred == 0) ? p0 : 0.0f;
        out[b * 4 + 1] = (pred == 1) ? p1 : 0.0f;
        out[b * 4 + 2] = (pred == 2) ? q0 : 0.0f;
        out[b * 4 + 3] = (pred == 2) ? q1 : 0.0f;
    }
}

// ---------------------------------------------------------------------------
extern "C" void kernel_launch(void* const* d_in, const int* in_sizes, int n_in,
                              void* d_out, int out_size)
{
    (void)in_sizes; (void)n_in; (void)out_size;
    const float* x = (const float*)d_in[0];

    const float* W[2][8];
    for (int net = 0; net < 2; net++)
        for (int i = 0; i < 8; i++)
            W[net][i] = (const float*)d_in[1 + net * 8 + i];

    float* out = (float*)d_out;

    float *a1, *feat;
    cudaGetSymbolAddress((void**)&a1, g_a1);
    cudaGetSymbolAddress((void**)&feat, g_feat);

    cudaFuncSetAttribute(conv2_mma_kernel,
                         cudaFuncAttributeMaxDynamicSharedMemorySize, C2_SMEM);

    zero_feat_kernel<<<1024, 256>>>();

    for (int net = 0; net < 2; net++) {
        conv01_kernel<<<dim3(512, 8), 256>>>(x, W[net][0], W[net][1],
                                             W[net][2], W[net][3], a1);
        conv2_mma_kernel<<<dim3(512, 4, 2), 256, C2_SMEM>>>(
            a1, W[net][4], W[net][5], feat + (size_t)net * 512 * 256);
    }

    head_kernel<<<512, 32>>>(W[0][6], W[0][7], W[1][6], W[1][7], out);
}

// round 7
// speedup vs baseline: 2.3412x; 1.9691x over previous
#include <cuda_runtime.h>
#include <math.h>

// ---------------------------------------------------------------------------
// HierarchicalCNN: two 3-layer strided conv1d nets + pooled heads + routing.
//
//   x    : [512, 2, 4096]
//   a1   : [512, 128, 1024]  (conv1 out fp32, scratch, reused per net)
//   feat : [2][512][256]     (pooled sums; /512 in head)
//   out  : [512, 4]
//
// conv0+conv1 fused (fma.rn.f32x2 path, proven R3 code).
// conv2 on tf32 mma.sync m16n8k8, SINGLE pass (rna-rounded operands,
// logit error ~1e-5 << 1e-3 threshold):
//   D[co,t] = sum over (ci, tap) of W[co,ci,tap] * a1[ci, 2t+tap-1]
// K streamed as 8 ci-chunks of 16 (x 5 taps). Activations staged ONCE per
// chunk into parity-split smem (even/odd input positions); taps select a
// row offset. Weights pre-converted/pre-tiled by a prep kernel so A staging
// is a raw float4 copy. Pool fused into epilogue.
// ---------------------------------------------------------------------------

typedef unsigned int       u32;
typedef unsigned long long ull;

__device__ float g_a1[(size_t)512 * 128 * 1024];
__device__ float g_feat[2][512][256];
// tf32-rounded conv2 weights: [net][coh][chunk][tap][co 128][ci 16]
__device__ __align__(16) float g_w2tf[2][2][8][5][128][16];

// ---------------- packed fp32x2 helpers (conv01 path) ----------------------
__device__ __forceinline__ void fma2(ull& d, ull a, ull b) {
    asm("fma.rn.f32x2 %0, %1, %2, %0;" : "+l"(d) : "l"(a), "l"(b));
}
__device__ __forceinline__ ull pack2(float lo, float hi) {
    ull r;
    asm("mov.b64 %0, {%1, %2};" : "=l"(r) : "f"(lo), "f"(hi));
    return r;
}
__device__ __forceinline__ void unpack2(ull v, float& lo, float& hi) {
    asm("mov.b64 {%0, %1}, %2;" : "=f"(lo), "=f"(hi) : "l"(v));
}

// ---------------- tf32 mma helpers -----------------------------------------
__device__ __forceinline__ u32 to_tf32(float v) {
    u32 r;
    asm("cvt.rna.tf32.f32 %0, %1;" : "=r"(r) : "f"(v));
    return r;
}
__device__ __forceinline__ void mma_tf32(float* d, const u32* a, u32 b0, u32 b1) {
    asm volatile(
        "mma.sync.aligned.m16n8k8.row.col.f32.tf32.tf32.f32 "
        "{%0,%1,%2,%3}, {%4,%5,%6,%7}, {%8,%9}, {%0,%1,%2,%3};"
        : "+f"(d[0]), "+f"(d[1]), "+f"(d[2]), "+f"(d[3])
        : "r"(a[0]), "r"(a[1]), "r"(a[2]), "r"(a[3]), "r"(b0), "r"(b1));
}

#define WPITCH 132

// ---------------------------------------------------------------------------
// conv01 (proven R3 fma2 path, unchanged)
// ---------------------------------------------------------------------------
__global__ __launch_bounds__(256, 2)
void conv01_kernel(const float* __restrict__ x,
                   const float* __restrict__ w0,  // [64,2,5]
                   const float* __restrict__ b0,  // [64]
                   const float* __restrict__ w1,  // [128,64,5]
                   const float* __restrict__ b1,  // [128]
                   float* __restrict__ out)       // [512,128,1024]
{
    const int b   = blockIdx.x;
    const int tt0 = blockIdx.y * 128;
    const int tid = threadIdx.x;
    const int tx  = tid & 15;
    const int ty  = tid >> 4;

    const int tmid0 = 2 * tt0 - 1;
    const int x0    = 2 * tmid0 - 1;

    __shared__ float xs0[2][524];
    __shared__ float w0s[64 * 10];
    __shared__ float b0s[64];
    __shared__ float ws[40][WPITCH];
    __shared__ float xs[8][260];

    for (int i = tid; i < 640; i += 256) w0s[i] = w0[i];
    if (tid < 64) b0s[tid] = b0[tid];

    const float* xb = x + (size_t)b * 2 * 4096;
    for (int i = tid; i < 2 * 524; i += 256) {
        int row = i / 524, col = i % 524;
        int gx = x0 + col;
        xs0[row][col] = (gx >= 0 && gx < 4096) ? xb[(size_t)row * 4096 + gx] : 0.0f;
    }

    ull acc2[4][8];
#pragma unroll
    for (int i = 0; i < 4; i++)
#pragma unroll
        for (int j = 0; j < 8; j++) acc2[i][j] = 0ull;

    __syncthreads();

    for (int ci0 = 0; ci0 < 64; ci0 += 8) {
#pragma unroll
        for (int r = 0; r < 20; r++) {
            int flat = r * 256 + tid;
            int co = flat / 40;
            int kk = flat % 40;
            ws[kk][co] = w1[(size_t)co * (64 * 5) + ci0 * 5 + kk];
        }
        for (int i = tid; i < 8 * 260; i += 256) {
            int row = i / 260, col = i % 260;
            int ci = ci0 + row;
            int tmid = tmid0 + col;
            float v = 0.0f;
            if (tmid >= 0 && tmid < 2048) {
                float a = b0s[ci];
                const float* wc = &w0s[ci * 10];
#pragma unroll
                for (int k = 0; k < 5; k++) a = fmaf(wc[k],     xs0[0][2 * col + k], a);
#pragma unroll
                for (int k = 0; k < 5; k++) a = fmaf(wc[5 + k], xs0[1][2 * col + k], a);
                v = fmaxf(a, 0.0f);
            }
            xs[row][col] = v;
        }
        __syncthreads();

#pragma unroll
        for (int ci = 0; ci < 8; ci++) {
#pragma unroll
            for (int k = 0; k < 5; k++) {
                const float4* wr =
                    reinterpret_cast<const float4*>(&ws[ci * 5 + k][ty * 8]);
                float4 al = wr[0], ah = wr[1];
                ull a2[4];
                a2[0] = pack2(al.x, al.y);
                a2[1] = pack2(al.z, al.w);
                a2[2] = pack2(ah.x, ah.y);
                a2[3] = pack2(ah.z, ah.w);
                ull b2[8];
#pragma unroll
                for (int j = 0; j < 8; j++) {
                    float bv = xs[ci][2 * (tx + 16 * j) + k];
                    b2[j] = pack2(bv, bv);
                }
#pragma unroll
                for (int cp = 0; cp < 4; cp++)
#pragma unroll
                    for (int tj = 0; tj < 8; tj++)
                        fma2(acc2[cp][tj], a2[cp], b2[tj]);
            }
        }
        __syncthreads();
    }

#pragma unroll
    for (int cp = 0; cp < 4; cp++) {
        int co_lo = ty * 8 + 2 * cp;
        float bl = b1[co_lo], bh = b1[co_lo + 1];
        float* ol = out + ((size_t)b * 128 + co_lo) * 1024 + tt0;
        float* oh = ol + 1024;
#pragma unroll
        for (int tj = 0; tj < 8; tj++) {
            float lo, hi;
            unpack2(acc2[cp][tj], lo, hi);
            int t = tx + 16 * tj;
            ol[t] = fmaxf(lo + bl, 0.0f);
            oh[t] = fmaxf(hi + bh, 0.0f);
        }
    }
}

// ---------------------------------------------------------------------------
// prep_w2: tf32-round conv2 weights into per-(chunk,tap) contiguous tiles.
// dest layout: [net][coh][chunk][tap][co 128][ci 16]
// ---------------------------------------------------------------------------
__global__ __launch_bounds__(256)
void prep_w2_kernel(const float* __restrict__ w_n0, const float* __restrict__ w_n1)
{
    int idx = blockIdx.x * 256 + threadIdx.x;
    const int total = 2 * 2 * 8 * 5 * 128 * 16;
    if (idx >= total) return;
    int r = idx;
    int ci = r & 15;   r >>= 4;
    int co = r & 127;  r >>= 7;
    int tap = r % 5;   r /= 5;
    int chunk = r & 7; r >>= 3;
    int coh = r & 1;   r >>= 1;
    int net = r;
    const float* w = net ? w_n1 : w_n0;
    float v = w[(size_t)(coh * 128 + co) * 640 + (chunk * 16 + ci) * 5 + tap];
    ((float*)g_w2tf)[idx] = __uint_as_float(to_tf32(v));
}

// ---------------------------------------------------------------------------
// conv2 via tf32 warp-MMA + fused pool.
// grid (512 b, 4 t-tiles, 2 co-halves), 256 threads (8 warps).
// CTA tile 128co x 128t; warp tile 32co x 64t (4 co-groups x 2 t-groups).
//
// smem (dynamic, pitch 20 floats -> (20r+c)%32 conflict-free LDS):
//   A  [tap 5][co 128][ci 16]   tf32 floats (copied from prep'd gmem)
//   Be [row 132][ci 16]         even input positions (g = 2*tt0 + 2*ie)
//   Bo [row 132][ci 16]         odd  input positions (g = 2*tt0 + 2*io - 1)
// tap -> (parity, row offset): k0:(odd,0) k1:(even,0) k2:(odd,1)
//                              k3:(even,1) k4:(odd,2)
// ---------------------------------------------------------------------------
#define PITCH 20
#define OFF_A  0
#define A_FLTS (5 * 128 * PITCH)          // 12800
#define OFF_BE A_FLTS
#define B_FLTS (132 * PITCH)              // 2640
#define OFF_BO (OFF_BE + B_FLTS)
#define C2_SMEM ((OFF_BO + B_FLTS) * 4)   // 72,320 bytes

__global__ __launch_bounds__(256, 2)
void conv2_mma_kernel(const float* __restrict__ in,    // [512,128,1024] fp32
                      const float* __restrict__ bias,  // [256]
                      float* __restrict__ feat,        // [512,256] sums
                      int net)
{
    extern __shared__ float sm[];
    float* As = sm + OFF_A;
    float* Be = sm + OFF_BE;
    float* Bo = sm + OFF_BO;

    const int tid  = threadIdx.x;
    const int wid  = tid >> 5;
    const int lane = tid & 31;
    const int b    = blockIdx.x;
    const int tt0  = blockIdx.y * 128;
    const int co0  = blockIdx.z * 128;

    const int wco = (wid & 3) * 32;   // warp co offset in tile
    const int wt  = (wid >> 2) * 64;  // warp t offset in tile
    const int lr  = lane >> 2;        // fragment row lane
    const int lc  = lane & 3;         // fragment col lane

    float acc[2][8][4];
#pragma unroll
    for (int m = 0; m < 2; m++)
#pragma unroll
        for (int j = 0; j < 8; j++)
#pragma unroll
            for (int e = 0; e < 4; e++) acc[m][j][e] = 0.0f;

    const float* inb = in + (size_t)b * 128 * 1024;
    // B staging decomposition: ci = tid>>4, row-lane = tid&15
    const int bci = tid >> 4;
    const int brl = tid & 15;

    for (int chunk = 0; chunk < 8; chunk++) {
        const int ci0 = chunk * 16;
        // ---- A stage: raw float4 copy of prep'd tile [5][128][16] ----
        {
            const float4* src = (const float4*)&g_w2tf[net][co0 >> 7][chunk][0][0][0];
#pragma unroll
            for (int r = 0; r < 10; r++) {
                int i = r * 256 + tid;       // 2560 float4
                int row = i >> 2, seg = i & 3;
                *(float4*)&As[row * PITCH + seg * 4] = src[i];
            }
        }
        // ---- B stage: parity-split window, tf32-rounded ----
        {
            const float* arow = inb + (size_t)(ci0 + bci) * 1024;
#pragma unroll
            for (int m = brl; m < 129; m += 16) {
                int g0 = 2 * tt0 + 2 * m;
                float ev = 0.0f, od = 0.0f;
                if (g0 < 1024) {
                    float2 v = *(const float2*)&arow[g0];
                    ev = v.x; od = v.y;
                }
                Be[m * PITCH + bci]       = __uint_as_float(to_tf32(ev));
                Bo[(m + 1) * PITCH + bci] = __uint_as_float(to_tf32(od));
            }
            if (tid < 16) {  // odd row 0: g = 2*tt0 - 1
                float v = (tt0 > 0) ? inb[(size_t)(ci0 + tid) * 1024 + 2 * tt0 - 1] : 0.0f;
                Bo[tid] = __uint_as_float(to_tf32(v));
            }
        }
        __syncthreads();

        // ---- mainloop: 5 taps x 2 k8-halves x (2 m x 8 j) mma ----
#pragma unroll
        for (int tap = 0; tap < 5; tap++) {
            const float* Bb = (tap == 1 || tap == 3) ? Be : Bo;
            const int roff = (tap == 0 || tap == 1) ? 0 : ((tap == 4) ? 2 : 1);

            u32 a[2][2][4];
#pragma unroll
            for (int m = 0; m < 2; m++) {
                const float* ab = As + (tap * 128 + wco + m * 16 + lr) * PITCH + lc;
#pragma unroll
                for (int h = 0; h < 2; h++) {
                    a[m][h][0] = __float_as_uint(ab[h * 8]);
                    a[m][h][1] = __float_as_uint(ab[8 * PITCH + h * 8]);
                    a[m][h][2] = __float_as_uint(ab[h * 8 + 4]);
                    a[m][h][3] = __float_as_uint(ab[8 * PITCH + h * 8 + 4]);
                }
            }
#pragma unroll
            for (int j = 0; j < 8; j++) {
                const float* bb = Bb + (wt + j * 8 + lr + roff) * PITCH + lc;
#pragma unroll
                for (int h = 0; h < 2; h++) {
                    u32 b0 = __float_as_uint(bb[h * 8]);
                    u32 b1 = __float_as_uint(bb[h * 8 + 4]);
                    mma_tf32(acc[0][j], a[0][h], b0, b1);
                    mma_tf32(acc[1][j], a[1][h], b0, b1);
                }
            }
        }
        __syncthreads();
    }

    // ---- epilogue: bias+relu per element, sum over t, quad-reduce, atomic ----
    float* fb = feat + (size_t)b * 256;
#pragma unroll
    for (int m = 0; m < 2; m++) {
        int r0 = co0 + wco + m * 16 + lr;
        int r1 = r0 + 8;
        float bv0 = __ldg(&bias[r0]);
        float bv1 = __ldg(&bias[r1]);
        float s0 = 0.0f, s1 = 0.0f;
#pragma unroll
        for (int j = 0; j < 8; j++) {
            s0 += fmaxf(acc[m][j][0] + bv0, 0.0f) + fmaxf(acc[m][j][1] + bv0, 0.0f);
            s1 += fmaxf(acc[m][j][2] + bv1, 0.0f) + fmaxf(acc[m][j][3] + bv1, 0.0f);
        }
        s0 += __shfl_xor_sync(0xffffffffu, s0, 1);
        s0 += __shfl_xor_sync(0xffffffffu, s0, 2);
        s1 += __shfl_xor_sync(0xffffffffu, s1, 1);
        s1 += __shfl_xor_sync(0xffffffffu, s1, 2);
        if (lc == 0) {
            atomicAdd(&fb[r0], s0);
            atomicAdd(&fb[r1], s1);
        }
    }
}

// ---------------------------------------------------------------------------
__global__ void zero_feat_kernel()
{
    int i = blockIdx.x * 256 + threadIdx.x;
    if (i < 2 * 512 * 256) ((float*)g_feat)[i] = 0.0f;
}

// ---------------------------------------------------------------------------
// heads + softmax + hierarchical routing. 1 warp per sample.
// ---------------------------------------------------------------------------
__global__ __launch_bounds__(32)
void head_kernel(const float* __restrict__ wh1, const float* __restrict__ bh1,
                 const float* __restrict__ wh2, const float* __restrict__ bh2,
                 float* __restrict__ out)
{
    const int b = blockIdx.x;
    const int lane = threadIdx.x;
    const float* f1 = &g_feat[0][b][0];
    const float* f2 = &g_feat[1][b][0];
    const float inv_pool = 1.0f / 512.0f;

    float lg1[3], lg2[2];
#pragma unroll
    for (int cls = 0; cls < 3; cls++) {
        float s = 0.0f;
        for (int c = lane; c < 256; c += 32) s += f1[c] * wh1[cls * 256 + c];
#pragma unroll
        for (int off = 16; off > 0; off >>= 1) s += __shfl_xor_sync(0xffffffffu, s, off);
        lg1[cls] = s * inv_pool + bh1[cls];
    }
#pragma unroll
    for (int cls = 0; cls < 2; cls++) {
        float s = 0.0f;
        for (int c = lane; c < 256; c += 32) s += f2[c] * wh2[cls * 256 + c];
#pragma unroll
        for (int off = 16; off > 0; off >>= 1) s += __shfl_xor_sync(0xffffffffu, s, off);
        lg2[cls] = s * inv_pool + bh2[cls];
    }

    if (lane == 0) {
        float m = fmaxf(lg1[0], fmaxf(lg1[1], lg1[2]));
        float e0 = expf(lg1[0] - m), e1 = expf(lg1[1] - m), e2 = expf(lg1[2] - m);
        float inv = 1.0f / (e0 + e1 + e2);
        float p0 = e0 * inv, p1 = e1 * inv, p2 = e2 * inv;
        int pred = 0; float best = p0;
        if (p1 > best) { best = p1; pred = 1; }
        if (p2 > best) { best = p2; pred = 2; }

        float m2 = fmaxf(lg2[0], lg2[1]);
        float q0 = expf(lg2[0] - m2), q1 = expf(lg2[1] - m2);
        float inv2 = 1.0f / (q0 + q1);
        q0 *= inv2; q1 *= inv2;

        out[b * 4 + 0] = (pred == 0) ? p0 : 0.0f;
        out[b * 4 + 1] = (pred == 1) ? p1 : 0.0f;
        out[b * 4 + 2] = (pred == 2) ? q0 : 0.0f;
        out[b * 4 + 3] = (pred == 2) ? q1 : 0.0f;
    }
}

// ---------------------------------------------------------------------------
extern "C" void kernel_launch(void* const* d_in, const int* in_sizes, int n_in,
                              void* d_out, int out_size)
{
    (void)in_sizes; (void)n_in; (void)out_size;
    const float* x = (const float*)d_in[0];

    const float* W[2][8];
    for (int net = 0; net < 2; net++)
        for (int i = 0; i < 8; i++)
            W[net][i] = (const float*)d_in[1 + net * 8 + i];

    float* out = (float*)d_out;

    float *a1, *feat;
    cudaGetSymbolAddress((void**)&a1, g_a1);
    cudaGetSymbolAddress((void**)&feat, g_feat);

    cudaFuncSetAttribute(conv2_mma_kernel,
                         cudaFuncAttributeMaxDynamicSharedMemorySize, C2_SMEM);

    zero_feat_kernel<<<1024, 256>>>();
    prep_w2_kernel<<<1280, 256>>>(W[0][4], W[1][4]);

    for (int net = 0; net < 2; net++) {
        conv01_kernel<<<dim3(512, 8), 256>>>(x, W[net][0], W[net][1],
                                             W[net][2], W[net][3], a1);
        conv2_mma_kernel<<<dim3(512, 4, 2), 256, C2_SMEM>>>(
            a1, W[net][5], feat + (size_t)net * 512 * 256, net);
    }

    head_kernel<<<512, 32>>>(W[0][6], W[0][7], W[1][6], W[1][7], out);
}

// round 8
// speedup vs baseline: 3.8384x; 1.6395x over previous
#include <cuda_runtime.h>
#include <math.h>

// ---------------------------------------------------------------------------
// HierarchicalCNN: two 3-layer strided conv1d nets + pooled heads + routing.
//
//   x    : [512, 2, 4096]
//   a1   : [512, 128, 1024]  (conv1 out fp32, scratch, reused per net)
//   feat : [2][512][256]     (pooled sums; /512 in head)
//   out  : [512, 4]
//
// BOTH conv stages now run on tf32 mma.sync m16n8k8 (single pass, rna):
//   conv01: D[co,t] = sum_(ci<64,tap) W1[co,ci,tap] * a0[ci, 2t+tap-1]
//           with a0 = relu(conv0(x)) computed on the fly into parity-split
//           smem B tiles (no intermediate activation tensor).
//   conv2 : D[co,t] = sum_(ci<128,tap) W2[co,ci,tap] * a1[ci, 2t+tap-1],
//           pool fused into epilogue.
// Weights pre-rounded to tf32 and pre-tiled per (chunk,tap) by prep kernels
// so A staging is a raw float4 copy.
// tap -> (parity, row offset): k0:(odd,0) k1:(even,0) k2:(odd,1)
//                              k3:(even,1) k4:(odd,2)
// ---------------------------------------------------------------------------

typedef unsigned int       u32;
typedef unsigned long long ull;

__device__ float g_a1[(size_t)512 * 128 * 1024];
__device__ float g_feat[2][512][256];
// tf32 conv1 weights: [net][chunk 4][tap 5][co 128][ci 16]
__device__ __align__(16) float g_w1tf[2][4][5][128][16];
// tf32 conv2 weights: [net][coh 2][chunk 8][tap 5][co 128][ci 16]
__device__ __align__(16) float g_w2tf[2][2][8][5][128][16];

// ---------------- tf32 mma helpers -----------------------------------------
__device__ __forceinline__ u32 to_tf32(float v) {
    u32 r;
    asm("cvt.rna.tf32.f32 %0, %1;" : "=r"(r) : "f"(v));
    return r;
}
__device__ __forceinline__ void mma_tf32(float* d, const u32* a, u32 b0, u32 b1) {
    asm volatile(
        "mma.sync.aligned.m16n8k8.row.col.f32.tf32.tf32.f32 "
        "{%0,%1,%2,%3}, {%4,%5,%6,%7}, {%8,%9}, {%0,%1,%2,%3};"
        : "+f"(d[0]), "+f"(d[1]), "+f"(d[2]), "+f"(d[3])
        : "r"(a[0]), "r"(a[1]), "r"(a[2]), "r"(a[3]), "r"(b0), "r"(b1));
}

#define PITCH 20  // smem row pitch (floats): (20r+c)%32 -> conflict-free

// ---------------------------------------------------------------------------
// prep kernels: tf32-round weights into per-(chunk,tap) contiguous tiles.
// ---------------------------------------------------------------------------
__global__ __launch_bounds__(256)
void prep_w1_kernel(const float* __restrict__ w_n0, const float* __restrict__ w_n1)
{
    int idx = blockIdx.x * 256 + threadIdx.x;
    const int total = 2 * 4 * 5 * 128 * 16;
    if (idx >= total) return;
    int r = idx;
    int ci = r & 15;   r >>= 4;
    int co = r & 127;  r >>= 7;
    int tap = r % 5;   r /= 5;
    int chunk = r & 3; r >>= 2;
    int net = r;
    const float* w = net ? w_n1 : w_n0;
    float v = w[(size_t)co * 320 + (chunk * 16 + ci) * 5 + tap];
    ((float*)g_w1tf)[idx] = __uint_as_float(to_tf32(v));
}

__global__ __launch_bounds__(256)
void prep_w2_kernel(const float* __restrict__ w_n0, const float* __restrict__ w_n1)
{
    int idx = blockIdx.x * 256 + threadIdx.x;
    const int total = 2 * 2 * 8 * 5 * 128 * 16;
    if (idx >= total) return;
    int r = idx;
    int ci = r & 15;   r >>= 4;
    int co = r & 127;  r >>= 7;
    int tap = r % 5;   r /= 5;
    int chunk = r & 7; r >>= 3;
    int coh = r & 1;   r >>= 1;
    int net = r;
    const float* w = net ? w_n1 : w_n0;
    float v = w[(size_t)(coh * 128 + co) * 640 + (chunk * 16 + ci) * 5 + tap];
    ((float*)g_w2tf)[idx] = __uint_as_float(to_tf32(v));
}

// ---------------------------------------------------------------------------
// conv01 via tf32 warp-MMA; conv0 computed on the fly into B tiles.
// grid (512 b, 8 t-tiles), 256 threads (8 warps).
// CTA tile 128co x 128t; warp tile 32co x 64t.
//
// smem (dynamic floats):
//   As [tap 5][co 128][16 @PITCH]  (copied from g_w1tf)
//   Be [132][16 @PITCH]  a0 at even times: Be[m] = a0(2*tt0 + 2m)
//   Bo [132][16 @PITCH]  a0 at odd  times: Bo[m] = a0(2*tt0 + 2m - 1)
//   xs0[2][524]  raw x window, x0 = 4*tt0 - 3
//   w0s[640], b0s[64]
// a0(ci,tau): x window col base cb = 2*tau - 4*tt0 + 2.
// ---------------------------------------------------------------------------
#define A_FLTS (5 * 128 * PITCH)          // 12800
#define B_FLTS (132 * PITCH)              // 2640
#define O1_BE  A_FLTS
#define O1_BO  (O1_BE + B_FLTS)
#define O1_X   (O1_BO + B_FLTS)           // 2*524 = 1048
#define O1_W0  (O1_X + 1048)              // 640
#define O1_B0  (O1_W0 + 640)              // 64
#define C1_SMEM ((O1_B0 + 64) * 4)        // 79,328 bytes

__global__ __launch_bounds__(256, 2)
void conv01_mma_kernel(const float* __restrict__ x,
                       const float* __restrict__ w0,  // [64,2,5]
                       const float* __restrict__ b0,  // [64]
                       const float* __restrict__ b1,  // [128]
                       float* __restrict__ out,       // [512,128,1024]
                       int net)
{
    extern __shared__ float sm[];
    float* As  = sm;
    float* Be  = sm + O1_BE;
    float* Bo  = sm + O1_BO;
    float* xs0 = sm + O1_X;
    float* w0s = sm + O1_W0;
    float* b0s = sm + O1_B0;

    const int tid  = threadIdx.x;
    const int wid  = tid >> 5;
    const int lane = tid & 31;
    const int b    = blockIdx.x;
    const int tt0  = blockIdx.y * 128;

    const int wco = (wid & 3) * 32;
    const int wt  = (wid >> 2) * 64;
    const int lr  = lane >> 2;
    const int lc  = lane & 3;

    // constant-per-CTA loads
    for (int i = tid; i < 640; i += 256) w0s[i] = w0[i];
    if (tid < 64) b0s[tid] = b0[tid];
    {
        const int x0 = 4 * tt0 - 3;
        const float* xb = x + (size_t)b * 2 * 4096;
        for (int i = tid; i < 2 * 524; i += 256) {
            int row = i / 524, col = i % 524;
            int gx = x0 + col;
            xs0[row * 524 + col] =
                (gx >= 0 && gx < 4096) ? xb[(size_t)row * 4096 + gx] : 0.0f;
        }
    }

    float acc[2][8][4];
#pragma unroll
    for (int m = 0; m < 2; m++)
#pragma unroll
        for (int j = 0; j < 8; j++)
#pragma unroll
            for (int e = 0; e < 4; e++) acc[m][j][e] = 0.0f;

    __syncthreads();

    for (int chunk = 0; chunk < 4; chunk++) {
        const int ci0 = chunk * 16;
        // ---- A stage: raw float4 copy of prep'd tile [5][128][16] ----
        {
            const float4* src = (const float4*)&g_w1tf[net][chunk][0][0][0];
#pragma unroll
            for (int r = 0; r < 10; r++) {
                int i = r * 256 + tid;
                int row = i >> 2, seg = i & 3;
                *(float4*)&As[row * PITCH + seg * 4] = src[i];
            }
        }
        // ---- B stage: compute a0 on the fly, parity-split, tf32 ----
        // entries: Be rows 0..128 (129), Bo rows 0..129 (130) -> 259 rows x 16
        for (int i = tid; i < 259 * 16; i += 256) {
            int ci = i & 15;
            int r  = i >> 4;
            int tau, cb;
            float* dst;
            if (r < 129) {               // even: Be[r] = a0(2*tt0 + 2r)
                tau = 2 * tt0 + 2 * r;
                cb  = 4 * r + 2;
                dst = &Be[r * PITCH + ci];
            } else {                     // odd: Bo[mm] = a0(2*tt0 + 2mm - 1)
                int mm = r - 129;
                tau = 2 * tt0 + 2 * mm - 1;
                cb  = 4 * mm;
                dst = &Bo[mm * PITCH + ci];
            }
            float v = 0.0f;
            if (tau >= 0 && tau < 2048) {
                int cig = ci0 + ci;
                const float* wc = &w0s[cig * 10];
                float a = b0s[cig];
#pragma unroll
                for (int k = 0; k < 5; k++) a = fmaf(wc[k],     xs0[cb + k], a);
#pragma unroll
                for (int k = 0; k < 5; k++) a = fmaf(wc[5 + k], xs0[524 + cb + k], a);
                v = fmaxf(a, 0.0f);
            }
            *dst = __uint_as_float(to_tf32(v));
        }
        __syncthreads();

        // ---- mainloop ----
#pragma unroll
        for (int tap = 0; tap < 5; tap++) {
            const float* Bb = (tap == 1 || tap == 3) ? Be : Bo;
            const int roff = (tap == 0 || tap == 1) ? 0 : ((tap == 4) ? 2 : 1);

            u32 a[2][2][4];
#pragma unroll
            for (int m = 0; m < 2; m++) {
                const float* ab = As + (tap * 128 + wco + m * 16 + lr) * PITCH + lc;
#pragma unroll
                for (int h = 0; h < 2; h++) {
                    a[m][h][0] = __float_as_uint(ab[h * 8]);
                    a[m][h][1] = __float_as_uint(ab[8 * PITCH + h * 8]);
                    a[m][h][2] = __float_as_uint(ab[h * 8 + 4]);
                    a[m][h][3] = __float_as_uint(ab[8 * PITCH + h * 8 + 4]);
                }
            }
#pragma unroll
            for (int j = 0; j < 8; j++) {
                const float* bb = Bb + (wt + j * 8 + lr + roff) * PITCH + lc;
#pragma unroll
                for (int h = 0; h < 2; h++) {
                    u32 b0r = __float_as_uint(bb[h * 8]);
                    u32 b1r = __float_as_uint(bb[h * 8 + 4]);
                    mma_tf32(acc[0][j], a[0][h], b0r, b1r);
                    mma_tf32(acc[1][j], a[1][h], b0r, b1r);
                }
            }
        }
        __syncthreads();
    }

    // ---- epilogue: bias+relu, write a1. D map: co = wco+m*16+lr (+8),
    //      t = wt + j*8 + 2*lc (+1). float2 stores. ----
#pragma unroll
    for (int m = 0; m < 2; m++) {
        int co_a = wco + m * 16 + lr;
        int co_b = co_a + 8;
        float bva = b1[co_a];
        float bvb = b1[co_b];
        float* oa = out + ((size_t)b * 128 + co_a) * 1024 + tt0;
        float* ob = out + ((size_t)b * 128 + co_b) * 1024 + tt0;
#pragma unroll
        for (int j = 0; j < 8; j++) {
            int t = wt + j * 8 + 2 * lc;
            *(float2*)&oa[t] = make_float2(fmaxf(acc[m][j][0] + bva, 0.0f),
                                           fmaxf(acc[m][j][1] + bva, 0.0f));
            *(float2*)&ob[t] = make_float2(fmaxf(acc[m][j][2] + bvb, 0.0f),
                                           fmaxf(acc[m][j][3] + bvb, 0.0f));
        }
    }
}

// ---------------------------------------------------------------------------
// conv2 via tf32 warp-MMA + fused pool (proven R7 kernel, unchanged).
// grid (512 b, 4 t-tiles, 2 co-halves), 256 threads.
// ---------------------------------------------------------------------------
#define O2_BE  A_FLTS
#define O2_BO  (O2_BE + B_FLTS)
#define C2_SMEM ((O2_BO + B_FLTS) * 4)   // 72,320 bytes

__global__ __launch_bounds__(256, 2)
void conv2_mma_kernel(const float* __restrict__ in,    // [512,128,1024] fp32
                      const float* __restrict__ bias,  // [256]
                      float* __restrict__ feat,        // [512,256] sums
                      int net)
{
    extern __shared__ float sm[];
    float* As = sm;
    float* Be = sm + O2_BE;
    float* Bo = sm + O2_BO;

    const int tid  = threadIdx.x;
    const int wid  = tid >> 5;
    const int lane = tid & 31;
    const int b    = blockIdx.x;
    const int tt0  = blockIdx.y * 128;
    const int co0  = blockIdx.z * 128;

    const int wco = (wid & 3) * 32;
    const int wt  = (wid >> 2) * 64;
    const int lr  = lane >> 2;
    const int lc  = lane & 3;

    float acc[2][8][4];
#pragma unroll
    for (int m = 0; m < 2; m++)
#pragma unroll
        for (int j = 0; j < 8; j++)
#pragma unroll
            for (int e = 0; e < 4; e++) acc[m][j][e] = 0.0f;

    const float* inb = in + (size_t)b * 128 * 1024;
    const int bci = tid >> 4;
    const int brl = tid & 15;

    for (int chunk = 0; chunk < 8; chunk++) {
        const int ci0 = chunk * 16;
        {
            const float4* src = (const float4*)&g_w2tf[net][co0 >> 7][chunk][0][0][0];
#pragma unroll
            for (int r = 0; r < 10; r++) {
                int i = r * 256 + tid;
                int row = i >> 2, seg = i & 3;
                *(float4*)&As[row * PITCH + seg * 4] = src[i];
            }
        }
        {
            const float* arow = inb + (size_t)(ci0 + bci) * 1024;
#pragma unroll
            for (int m = brl; m < 129; m += 16) {
                int g0 = 2 * tt0 + 2 * m;
                float ev = 0.0f, od = 0.0f;
                if (g0 < 1024) {
                    float2 v = *(const float2*)&arow[g0];
                    ev = v.x; od = v.y;
                }
                Be[m * PITCH + bci]       = __uint_as_float(to_tf32(ev));
                Bo[(m + 1) * PITCH + bci] = __uint_as_float(to_tf32(od));
            }
            if (tid < 16) {
                float v = (tt0 > 0) ? inb[(size_t)(ci0 + tid) * 1024 + 2 * tt0 - 1] : 0.0f;
                Bo[tid] = __uint_as_float(to_tf32(v));
            }
        }
        __syncthreads();

#pragma unroll
        for (int tap = 0; tap < 5; tap++) {
            const float* Bb = (tap == 1 || tap == 3) ? Be : Bo;
            const int roff = (tap == 0 || tap == 1) ? 0 : ((tap == 4) ? 2 : 1);

            u32 a[2][2][4];
#pragma unroll
            for (int m = 0; m < 2; m++) {
                const float* ab = As + (tap * 128 + wco + m * 16 + lr) * PITCH + lc;
#pragma unroll
                for (int h = 0; h < 2; h++) {
                    a[m][h][0] = __float_as_uint(ab[h * 8]);
                    a[m][h][1] = __float_as_uint(ab[8 * PITCH + h * 8]);
                    a[m][h][2] = __float_as_uint(ab[h * 8 + 4]);
                    a[m][h][3] = __float_as_uint(ab[8 * PITCH + h * 8 + 4]);
                }
            }
#pragma unroll
            for (int j = 0; j < 8; j++) {
                const float* bb = Bb + (wt + j * 8 + lr + roff) * PITCH + lc;
#pragma unroll
                for (int h = 0; h < 2; h++) {
                    u32 b0 = __float_as_uint(bb[h * 8]);
                    u32 b1 = __float_as_uint(bb[h * 8 + 4]);
                    mma_tf32(acc[0][j], a[0][h], b0, b1);
                    mma_tf32(acc[1][j], a[1][h], b0, b1);
                }
            }
        }
        __syncthreads();
    }

    float* fb = feat + (size_t)b * 256;
#pragma unroll
    for (int m = 0; m < 2; m++) {
        int r0 = co0 + wco + m * 16 + lr;
        int r1 = r0 + 8;
        float bv0 = __ldg(&bias[r0]);
        float bv1 = __ldg(&bias[r1]);
        float s0 = 0.0f, s1 = 0.0f;
#pragma unroll
        for (int j = 0; j < 8; j++) {
            s0 += fmaxf(acc[m][j][0] + bv0, 0.0f) + fmaxf(acc[m][j][1] + bv0, 0.0f);
            s1 += fmaxf(acc[m][j][2] + bv1, 0.0f) + fmaxf(acc[m][j][3] + bv1, 0.0f);
        }
        s0 += __shfl_xor_sync(0xffffffffu, s0, 1);
        s0 += __shfl_xor_sync(0xffffffffu, s0, 2);
        s1 += __shfl_xor_sync(0xffffffffu, s1, 1);
        s1 += __shfl_xor_sync(0xffffffffu, s1, 2);
        if (lc == 0) {
            atomicAdd(&fb[r0], s0);
            atomicAdd(&fb[r1], s1);
        }
    }
}

// ---------------------------------------------------------------------------
__global__ void zero_feat_kernel()
{
    int i = blockIdx.x * 256 + threadIdx.x;
    if (i < 2 * 512 * 256) ((float*)g_feat)[i] = 0.0f;
}

// ---------------------------------------------------------------------------
// heads + softmax + hierarchical routing. 1 warp per sample.
// ---------------------------------------------------------------------------
__global__ __launch_bounds__(32)
void head_kernel(const float* __restrict__ wh1, const float* __restrict__ bh1,
                 const float* __restrict__ wh2, const float* __restrict__ bh2,
                 float* __restrict__ out)
{
    const int b = blockIdx.x;
    const int lane = threadIdx.x;
    const float* f1 = &g_feat[0][b][0];
    const float* f2 = &g_feat[1][b][0];
    const float inv_pool = 1.0f / 512.0f;

    float lg1[3], lg2[2];
#pragma unroll
    for (int cls = 0; cls < 3; cls++) {
        float s = 0.0f;
        for (int c = lane; c < 256; c += 32) s += f1[c] * wh1[cls * 256 + c];
#pragma unroll
        for (int off = 16; off > 0; off >>= 1) s += __shfl_xor_sync(0xffffffffu, s, off);
        lg1[cls] = s * inv_pool + bh1[cls];
    }
#pragma unroll
    for (int cls = 0; cls < 2; cls++) {
        float s = 0.0f;
        for (int c = lane; c < 256; c += 32) s += f2[c] * wh2[cls * 256 + c];
#pragma unroll
        for (int off = 16; off > 0; off >>= 1) s += __shfl_xor_sync(0xffffffffu, s, off);
        lg2[cls] = s * inv_pool + bh2[cls];
    }

    if (lane == 0) {
        float m = fmaxf(lg1[0], fmaxf(lg1[1], lg1[2]));
        float e0 = expf(lg1[0] - m), e1 = expf(lg1[1] - m), e2 = expf(lg1[2] - m);
        float inv = 1.0f / (e0 + e1 + e2);
        float p0 = e0 * inv, p1 = e1 * inv, p2 = e2 * inv;
        int pred = 0; float best = p0;
        if (p1 > best) { best = p1; pred = 1; }
        if (p2 > best) { best = p2; pred = 2; }

        float m2 = fmaxf(lg2[0], lg2[1]);
        float q0 = expf(lg2[0] - m2), q1 = expf(lg2[1] - m2);
        float inv2 = 1.0f / (q0 + q1);
        q0 *= inv2; q1 *= inv2;

        out[b * 4 + 0] = (pred == 0) ? p0 : 0.0f;
        out[b * 4 + 1] = (pred == 1) ? p1 : 0.0f;
        out[b * 4 + 2] = (pred == 2) ? q0 : 0.0f;
        out[b * 4 + 3] = (pred == 2) ? q1 : 0.0f;
    }
}

// ---------------------------------------------------------------------------
extern "C" void kernel_launch(void* const* d_in, const int* in_sizes, int n_in,
                              void* d_out, int out_size)
{
    (void)in_sizes; (void)n_in; (void)out_size;
    const float* x = (const float*)d_in[0];

    const float* W[2][8];
    for (int net = 0; net < 2; net++)
        for (int i = 0; i < 8; i++)
            W[net][i] = (const float*)d_in[1 + net * 8 + i];

    float* out = (float*)d_out;

    float *a1, *feat;
    cudaGetSymbolAddress((void**)&a1, g_a1);
    cudaGetSymbolAddress((void**)&feat, g_feat);

    cudaFuncSetAttribute(conv01_mma_kernel,
                         cudaFuncAttributeMaxDynamicSharedMemorySize, C1_SMEM);
    cudaFuncSetAttribute(conv2_mma_kernel,
                         cudaFuncAttributeMaxDynamicSharedMemorySize, C2_SMEM);

    zero_feat_kernel<<<1024, 256>>>();
    prep_w1_kernel<<<320, 256>>>(W[0][2], W[1][2]);
    prep_w2_kernel<<<1280, 256>>>(W[0][4], W[1][4]);

    for (int net = 0; net < 2; net++) {
        conv01_mma_kernel<<<dim3(512, 8), 256, C1_SMEM>>>(
            x, W[net][0], W[net][1], W[net][3], a1, net);
        conv2_mma_kernel<<<dim3(512, 4, 2), 256, C2_SMEM>>>(
            a1, W[net][5], feat + (size_t)net * 512 * 256, net);
    }

    head_kernel<<<512, 32>>>(W[0][6], W[0][7], W[1][6], W[1][7], out);
}

// round 9
// speedup vs baseline: 3.8931x; 1.0142x over previous
#include <cuda_runtime.h>
#include <math.h>

// ---------------------------------------------------------------------------
// HierarchicalCNN: two 3-layer strided conv1d nets + pooled heads + routing.
// Both conv stages on tf32 mma.sync m16n8k8 (single pass, rna).
//
// Smem layout for MMA tiles: column-interleaved, pitch 24 floats.
//   pos(ci) = (ci>>3)*8 + (ci&3)*2 + ((ci>>2)&1)
// puts k-pair (c, c+4) adjacent -> every fragment operand is one LDS.64;
// pitch 24 makes all fragment loads bank-conflict-free.
// tap -> (parity, row offset): k0:(odd,0) k1:(even,0) k2:(odd,1)
//                              k3:(even,1) k4:(odd,2)
// Weight tiles are pre-rounded/pre-interleaved in gmem and staged with
// cp.async (overlapping the B staging compute).
// ---------------------------------------------------------------------------

typedef unsigned int       u32;
typedef unsigned long long ull;

__device__ float g_a1[(size_t)512 * 128 * 1024];
__device__ float g_feat[2][512][256];
// tf32 conv1 weights, interleaved cols: [net][chunk 4][tap 5][co 128][pos 16]
__device__ __align__(16) float g_w1tf[2][4][5][128][16];
// tf32 conv2 weights: [net][coh 2][chunk 8][tap 5][co 128][pos 16]
__device__ __align__(16) float g_w2tf[2][2][8][5][128][16];

// ---------------- helpers ---------------------------------------------------
__device__ __forceinline__ u32 to_tf32(float v) {
    u32 r;
    asm("cvt.rna.tf32.f32 %0, %1;" : "=r"(r) : "f"(v));
    return r;
}
__device__ __forceinline__ void mma_tf32(float* d, const u32* a, u32 b0, u32 b1) {
    asm volatile(
        "mma.sync.aligned.m16n8k8.row.col.f32.tf32.tf32.f32 "
        "{%0,%1,%2,%3}, {%4,%5,%6,%7}, {%8,%9}, {%0,%1,%2,%3};"
        : "+f"(d[0]), "+f"(d[1]), "+f"(d[2]), "+f"(d[3])
        : "r"(a[0]), "r"(a[1]), "r"(a[2]), "r"(a[3]), "r"(b0), "r"(b1));
}
__device__ __forceinline__ u32 smem_u32(const void* p) {
    u32 a;
    asm("{ .reg .u64 t; cvta.to.shared.u64 t, %1; cvt.u32.u64 %0, t; }"
        : "=r"(a) : "l"(p));
    return a;
}
__device__ __forceinline__ void cp16(u32 dst, const void* src) {
    asm volatile("cp.async.cg.shared.global [%0], [%1], 16;" :: "r"(dst), "l"(src));
}
#define CP_COMMIT() asm volatile("cp.async.commit_group;" ::: "memory")
#define CP_WAIT0()  asm volatile("cp.async.wait_group 0;" ::: "memory")

__host__ __device__ constexpr int posi(int ci) {
    return ((ci >> 3) << 3) + ((ci & 3) << 1) + ((ci >> 2) & 1);
}

#define PITCH 24
#define A_FLTS (5 * 128 * PITCH)   // 15360
#define B_FLTS (132 * PITCH)       // 3168

// ---------------------------------------------------------------------------
// prep kernels: tf32-round + column-interleave weights into per-(chunk,tap)
// contiguous tiles.
// ---------------------------------------------------------------------------
__global__ __launch_bounds__(256)
void prep_w1_kernel(const float* __restrict__ w_n0, const float* __restrict__ w_n1)
{
    int idx = blockIdx.x * 256 + threadIdx.x;
    const int total = 2 * 4 * 5 * 128 * 16;
    if (idx >= total) return;
    int r = idx;
    int ci = r & 15;   r >>= 4;
    int co = r & 127;  r >>= 7;
    int tap = r % 5;   r /= 5;
    int chunk = r & 3; r >>= 2;
    int net = r;
    const float* w = net ? w_n1 : w_n0;
    float v = w[(size_t)co * 320 + (chunk * 16 + ci) * 5 + tap];
    g_w1tf[net][chunk][tap][co][posi(ci)] = __uint_as_float(to_tf32(v));
}

__global__ __launch_bounds__(256)
void prep_w2_kernel(const float* __restrict__ w_n0, const float* __restrict__ w_n1)
{
    int idx = blockIdx.x * 256 + threadIdx.x;
    const int total = 2 * 2 * 8 * 5 * 128 * 16;
    if (idx >= total) return;
    int r = idx;
    int ci = r & 15;   r >>= 4;
    int co = r & 127;  r >>= 7;
    int tap = r % 5;   r /= 5;
    int chunk = r & 7; r >>= 3;
    int coh = r & 1;   r >>= 1;
    int net = r;
    const float* w = net ? w_n1 : w_n0;
    float v = w[(size_t)(coh * 128 + co) * 640 + (chunk * 16 + ci) * 5 + tap];
    g_w2tf[net][coh][chunk][tap][co][posi(ci)] = __uint_as_float(to_tf32(v));
}

// ---------------------------------------------------------------------------
// shared mainloop fragment code (identical in both kernels)
// ---------------------------------------------------------------------------
#define MMA_MAINLOOP(As, Be, Bo)                                               \
    _Pragma("unroll")                                                          \
    for (int tap = 0; tap < 5; tap++) {                                        \
        const float* Bb = (tap == 1 || tap == 3) ? (Be) : (Bo);                \
        const int roff = (tap < 2) ? 0 : ((tap == 4) ? 2 : 1);                 \
        u32 a[2][2][4];                                                        \
        _Pragma("unroll")                                                      \
        for (int m = 0; m < 2; m++) {                                          \
            const float* ab = (As) + (tap * 128 + wco + m * 16 + lr) * PITCH + 2 * lc; \
            _Pragma("unroll")                                                  \
            for (int h = 0; h < 2; h++) {                                      \
                float2 q0 = *(const float2*)&ab[8 * h];                        \
                float2 q1 = *(const float2*)&ab[8 * PITCH + 8 * h];            \
                a[m][h][0] = __float_as_uint(q0.x);                            \
                a[m][h][1] = __float_as_uint(q1.x);                            \
                a[m][h][2] = __float_as_uint(q0.y);                            \
                a[m][h][3] = __float_as_uint(q1.y);                            \
            }                                                                  \
        }                                                                      \
        _Pragma("unroll")                                                      \
        for (int j = 0; j < 8; j++) {                                          \
            const float* bb = Bb + (wt + j * 8 + lr + roff) * PITCH + 2 * lc;  \
            _Pragma("unroll")                                                  \
            for (int h = 0; h < 2; h++) {                                      \
                float2 p = *(const float2*)&bb[8 * h];                         \
                u32 pb0 = __float_as_uint(p.x), pb1 = __float_as_uint(p.y);    \
                mma_tf32(acc[0][j], a[0][h], pb0, pb1);                        \
                mma_tf32(acc[1][j], a[1][h], pb0, pb1);                        \
            }                                                                  \
        }                                                                      \
    }

// ---------------------------------------------------------------------------
// conv01 via tf32 warp-MMA; conv0 computed on the fly into B tiles.
// grid (512 b, 8 t-tiles), 256 threads (8 warps). CTA 128co x 128t.
//
// smem (floats): As[5*128*24] | Be[132*24] | Bo[132*24] | xs0[2*524]
//                | w0s[64*12] | b0s[64]
// ---------------------------------------------------------------------------
#define O1_BE  A_FLTS
#define O1_BO  (O1_BE + B_FLTS)
#define O1_X   (O1_BO + B_FLTS)
#define O1_W0  (O1_X + 1048)
#define O1_B0  (O1_W0 + 768)
#define C1_SMEM ((O1_B0 + 64) * 4)     // 94,304 bytes

__global__ __launch_bounds__(256, 2)
void conv01_mma_kernel(const float* __restrict__ x,
                       const float* __restrict__ w0,  // [64,2,5]
                       const float* __restrict__ b0,  // [64]
                       const float* __restrict__ b1,  // [128]
                       float* __restrict__ out,       // [512,128,1024]
                       int net)
{
    extern __shared__ float sm[];
    float* As  = sm;
    float* Be  = sm + O1_BE;
    float* Bo  = sm + O1_BO;
    float* xs0 = sm + O1_X;
    float* w0s = sm + O1_W0;   // padded [64][12]
    float* b0s = sm + O1_B0;

    const int tid  = threadIdx.x;
    const int wid  = tid >> 5;
    const int lane = tid & 31;
    const int b    = blockIdx.x;
    const int tt0  = blockIdx.y * 128;

    const int wco = (wid & 3) * 32;
    const int wt  = (wid >> 2) * 64;
    const int lr  = lane >> 2;
    const int lc  = lane & 3;
    const u32 uAs = smem_u32(As);

    // one-time CTA loads
    for (int i = tid; i < 640; i += 256)
        w0s[(i / 10) * 12 + (i % 10)] = w0[i];
    if (tid < 64) b0s[tid] = b0[tid];
    {
        const int x0 = 4 * tt0 - 3;
        const float* xb = x + (size_t)b * 2 * 4096;
        for (int i = tid; i < 2 * 524; i += 256) {
            int row = i / 524, col = i % 524;
            int gx = x0 + col;
            xs0[row * 524 + col] =
                (gx >= 0 && gx < 4096) ? xb[(size_t)row * 4096 + gx] : 0.0f;
        }
    }

    float acc[2][8][4];
#pragma unroll
    for (int m = 0; m < 2; m++)
#pragma unroll
        for (int j = 0; j < 8; j++)
#pragma unroll
            for (int e = 0; e < 4; e++) acc[m][j][e] = 0.0f;

    __syncthreads();

    for (int chunk = 0; chunk < 4; chunk++) {
        const int ci0 = chunk * 16;

        // ---- A stage: cp.async of prep'd tile (packed 16 -> pitch 24) ----
        {
            const char* src = (const char*)&g_w1tf[net][chunk][0][0][0];
#pragma unroll
            for (int r = 0; r < 10; r++) {
                int i = r * 256 + tid;
                int row = i >> 2, seg = i & 3;
                cp16(uAs + (u32)(row * PITCH + seg * 4) * 4, src + (size_t)i * 16);
            }
            CP_COMMIT();
        }

        // ---- B stage: one t-row per thread; x taps in regs; broadcast w ----
        for (int r = tid; r < 259; r += 256) {
            int tau, cb;
            float* dst;
            if (r < 129) {               // even rows: Be[r] = a0(2*tt0 + 2r)
                tau = 2 * tt0 + 2 * r;
                cb  = 4 * r + 2;
                dst = &Be[r * PITCH];
            } else {                     // odd rows: Bo[mm] = a0(2*tt0 + 2mm - 1)
                int mm = r - 129;
                tau = 2 * tt0 + 2 * mm - 1;
                cb  = 4 * mm;
                dst = &Bo[mm * PITCH];
            }
            u32 v[16];
            if (tau >= 0 && tau < 2048) {
                float xv[10];
#pragma unroll
                for (int k = 0; k < 5; k++) xv[k] = xs0[cb + k];
#pragma unroll
                for (int k = 0; k < 5; k++) xv[5 + k] = xs0[524 + cb + k];
#pragma unroll
                for (int ci = 0; ci < 16; ci++) {
                    const float* wc = &w0s[(ci0 + ci) * 12];
                    float4 wA = *(const float4*)wc;
                    float4 wB = *(const float4*)(wc + 4);
                    float2 wC = *(const float2*)(wc + 8);
                    float a = b0s[ci0 + ci];
                    a = fmaf(wA.x, xv[0], a); a = fmaf(wA.y, xv[1], a);
                    a = fmaf(wA.z, xv[2], a); a = fmaf(wA.w, xv[3], a);
                    a = fmaf(wB.x, xv[4], a); a = fmaf(wB.y, xv[5], a);
                    a = fmaf(wB.z, xv[6], a); a = fmaf(wB.w, xv[7], a);
                    a = fmaf(wC.x, xv[8], a); a = fmaf(wC.y, xv[9], a);
                    v[posi(ci)] = to_tf32(fmaxf(a, 0.0f));
                }
            } else {
#pragma unroll
                for (int i = 0; i < 16; i++) v[i] = 0u;
            }
#pragma unroll
            for (int s = 0; s < 4; s++)
                *(float4*)&dst[4 * s] = make_float4(
                    __uint_as_float(v[4 * s]),     __uint_as_float(v[4 * s + 1]),
                    __uint_as_float(v[4 * s + 2]), __uint_as_float(v[4 * s + 3]));
        }
        CP_WAIT0();
        __syncthreads();

        MMA_MAINLOOP(As, Be, Bo)
        __syncthreads();
    }

    // ---- epilogue: bias+relu, write a1; t = wt + j*8 + 2lc (+1) ----
#pragma unroll
    for (int m = 0; m < 2; m++) {
        int co_a = wco + m * 16 + lr;
        int co_b = co_a + 8;
        float bva = b1[co_a];
        float bvb = b1[co_b];
        float* oa = out + ((size_t)b * 128 + co_a) * 1024 + tt0;
        float* ob = out + ((size_t)b * 128 + co_b) * 1024 + tt0;
#pragma unroll
        for (int j = 0; j < 8; j++) {
            int t = wt + j * 8 + 2 * lc;
            *(float2*)&oa[t] = make_float2(fmaxf(acc[m][j][0] + bva, 0.0f),
                                           fmaxf(acc[m][j][1] + bva, 0.0f));
            *(float2*)&ob[t] = make_float2(fmaxf(acc[m][j][2] + bvb, 0.0f),
                                           fmaxf(acc[m][j][3] + bvb, 0.0f));
        }
    }
}

// ---------------------------------------------------------------------------
// conv2 via tf32 warp-MMA + fused pool. grid (512 b, 4 tq, 2 coh), 256 thr.
// smem (floats): As[5*128*24] | Be[132*24] | Bo[132*24]
// ---------------------------------------------------------------------------
#define O2_BE  A_FLTS
#define O2_BO  (O2_BE + B_FLTS)
#define C2_SMEM ((O2_BO + B_FLTS) * 4)  // 86,784 bytes

__global__ __launch_bounds__(256, 2)
void conv2_mma_kernel(const float* __restrict__ in,    // [512,128,1024] fp32
                      const float* __restrict__ bias,  // [256]
                      float* __restrict__ feat,        // [512,256] sums
                      int net)
{
    extern __shared__ float sm[];
    float* As = sm;
    float* Be = sm + O2_BE;
    float* Bo = sm + O2_BO;

    const int tid  = threadIdx.x;
    const int wid  = tid >> 5;
    const int lane = tid & 31;
    const int b    = blockIdx.x;
    const int tt0  = blockIdx.y * 128;
    const int co0  = blockIdx.z * 128;

    const int wco = (wid & 3) * 32;
    const int wt  = (wid >> 2) * 64;
    const int lr  = lane >> 2;
    const int lc  = lane & 3;
    const u32 uAs = smem_u32(As);

    float acc[2][8][4];
#pragma unroll
    for (int m = 0; m < 2; m++)
#pragma unroll
        for (int j = 0; j < 8; j++)
#pragma unroll
            for (int e = 0; e < 4; e++) acc[m][j][e] = 0.0f;

    const float* inb = in + (size_t)b * 128 * 1024;
    const int bci  = tid >> 4;          // staged ci (0..15)
    const int brl  = tid & 15;          // row lane
    const int pcol = posi(bci);

    for (int chunk = 0; chunk < 8; chunk++) {
        const int ci0 = chunk * 16;
        // ---- A stage: cp.async ----
        {
            const char* src = (const char*)&g_w2tf[net][co0 >> 7][chunk][0][0][0];
#pragma unroll
            for (int r = 0; r < 10; r++) {
                int i = r * 256 + tid;
                int row = i >> 2, seg = i & 3;
                cp16(uAs + (u32)(row * PITCH + seg * 4) * 4, src + (size_t)i * 16);
            }
            CP_COMMIT();
        }
        // ---- B stage: parity-split copy + tf32 ----
        {
            const float* arow = inb + (size_t)(ci0 + bci) * 1024;
            for (int m = brl; m < 129; m += 16) {
                int g0 = 2 * tt0 + 2 * m;
                float ev = 0.0f, od = 0.0f;
                if (g0 < 1024) {
                    float2 v = *(const float2*)&arow[g0];
                    ev = v.x; od = v.y;
                }
                Be[m * PITCH + pcol]       = __uint_as_float(to_tf32(ev));
                Bo[(m + 1) * PITCH + pcol] = __uint_as_float(to_tf32(od));
            }
            if (tid < 16) {  // odd row 0: g = 2*tt0 - 1
                float v = (tt0 > 0) ? inb[(size_t)(ci0 + tid) * 1024 + 2 * tt0 - 1] : 0.0f;
                Bo[posi(tid)] = __uint_as_float(to_tf32(v));
            }
        }
        CP_WAIT0();
        __syncthreads();

        MMA_MAINLOOP(As, Be, Bo)
        __syncthreads();
    }

    // ---- epilogue: bias+relu, sum over t, quad-reduce, atomicAdd ----
    float* fb = feat + (size_t)b * 256;
#pragma unroll
    for (int m = 0; m < 2; m++) {
        int r0 = co0 + wco + m * 16 + lr;
        int r1 = r0 + 8;
        float bv0 = __ldg(&bias[r0]);
        float bv1 = __ldg(&bias[r1]);
        float s0 = 0.0f, s1 = 0.0f;
#pragma unroll
        for (int j = 0; j < 8; j++) {
            s0 += fmaxf(acc[m][j][0] + bv0, 0.0f) + fmaxf(acc[m][j][1] + bv0, 0.0f);
            s1 += fmaxf(acc[m][j][2] + bv1, 0.0f) + fmaxf(acc[m][j][3] + bv1, 0.0f);
        }
        s0 += __shfl_xor_sync(0xffffffffu, s0, 1);
        s0 += __shfl_xor_sync(0xffffffffu, s0, 2);
        s1 += __shfl_xor_sync(0xffffffffu, s1, 1);
        s1 += __shfl_xor_sync(0xffffffffu, s1, 2);
        if (lc == 0) {
            atomicAdd(&fb[r0], s0);
            atomicAdd(&fb[r1], s1);
        }
    }
}

// ---------------------------------------------------------------------------
__global__ void zero_feat_kernel()
{
    int i = blockIdx.x * 256 + threadIdx.x;
    if (i < 2 * 512 * 256) ((float*)g_feat)[i] = 0.0f;
}

// ---------------------------------------------------------------------------
// heads + softmax + hierarchical routing. 1 warp per sample.
// ---------------------------------------------------------------------------
__global__ __launch_bounds__(32)
void head_kernel(const float* __restrict__ wh1, const float* __restrict__ bh1,
                 const float* __restrict__ wh2, const float* __restrict__ bh2,
                 float* __restrict__ out)
{
    const int b = blockIdx.x;
    const int lane = threadIdx.x;
    const float* f1 = &g_feat[0][b][0];
    const float* f2 = &g_feat[1][b][0];
    const float inv_pool = 1.0f / 512.0f;

    float lg1[3], lg2[2];
#pragma unroll
    for (int cls = 0; cls < 3; cls++) {
        float s = 0.0f;
        for (int c = lane; c < 256; c += 32) s += f1[c] * wh1[cls * 256 + c];
#pragma unroll
        for (int off = 16; off > 0; off >>= 1) s += __shfl_xor_sync(0xffffffffu, s, off);
        lg1[cls] = s * inv_pool + bh1[cls];
    }
#pragma unroll
    for (int cls = 0; cls < 2; cls++) {
        float s = 0.0f;
        for (int c = lane; c < 256; c += 32) s += f2[c] * wh2[cls * 256 + c];
#pragma unroll
        for (int off = 16; off > 0; off >>= 1) s += __shfl_xor_sync(0xffffffffu, s, off);
        lg2[cls] = s * inv_pool + bh2[cls];
    }

    if (lane == 0) {
        float m = fmaxf(lg1[0], fmaxf(lg1[1], lg1[2]));
        float e0 = expf(lg1[0] - m), e1 = expf(lg1[1] - m), e2 = expf(lg1[2] - m);
        float inv = 1.0f / (e0 + e1 + e2);
        float p0 = e0 * inv, p1 = e1 * inv, p2 = e2 * inv;
        int pred = 0; float best = p0;
        if (p1 > best) { best = p1; pred = 1; }
        if (p2 > best) { best = p2; pred = 2; }

        float m2 = fmaxf(lg2[0], lg2[1]);
        float q0 = expf(lg2[0] - m2), q1 = expf(lg2[1] - m2);
        float inv2 = 1.0f / (q0 + q1);
        q0 *= inv2; q1 *= inv2;

        out[b * 4 + 0] = (pred == 0) ? p0 : 0.0f;
        out[b * 4 + 1] = (pred == 1) ? p1 : 0.0f;
        out[b * 4 + 2] = (pred == 2) ? q0 : 0.0f;
        out[b * 4 + 3] = (pred == 2) ? q1 : 0.0f;
    }
}

// ---------------------------------------------------------------------------
extern "C" void kernel_launch(void* const* d_in, const int* in_sizes, int n_in,
                              void* d_out, int out_size)
{
    (void)in_sizes; (void)n_in; (void)out_size;
    const float* x = (const float*)d_in[0];

    const float* W[2][8];
    for (int net = 0; net < 2; net++)
        for (int i = 0; i < 8; i++)
            W[net][i] = (const float*)d_in[1 + net * 8 + i];

    float* out = (float*)d_out;

    float *a1, *feat;
    cudaGetSymbolAddress((void**)&a1, g_a1);
    cudaGetSymbolAddress((void**)&feat, g_feat);

    cudaFuncSetAttribute(conv01_mma_kernel,
                         cudaFuncAttributeMaxDynamicSharedMemorySize, C1_SMEM);
    cudaFuncSetAttribute(conv2_mma_kernel,
                         cudaFuncAttributeMaxDynamicSharedMemorySize, C2_SMEM);

    zero_feat_kernel<<<1024, 256>>>();
    prep_w1_kernel<<<320, 256>>>(W[0][2], W[1][2]);
    prep_w2_kernel<<<1280, 256>>>(W[0][4], W[1][4]);

    for (int net = 0; net < 2; net++) {
        conv01_mma_kernel<<<dim3(512, 8), 256, C1_SMEM>>>(
            x, W[net][0], W[net][1], W[net][3], a1, net);
        conv2_mma_kernel<<<dim3(512, 4, 2), 256, C2_SMEM>>>(
            a1, W[net][5], feat + (size_t)net * 512 * 256, net);
    }

    head_kernel<<<512, 32>>>(W[0][6], W[0][7], W[1][6], W[1][7], out);
}

// round 10
// speedup vs baseline: 3.9436x; 1.0130x over previous
#include <cuda_runtime.h>
#include <math.h>

// ---------------------------------------------------------------------------
// HierarchicalCNN: two 3-layer strided conv1d nets + pooled heads + routing.
// Both conv stages on tf32 mma.sync m16n8k8 (single pass, rna).
//
// Smem layout for MMA tiles: column-interleaved, pitch 24 floats.
//   pos(ci) = (ci>>3)*8 + (ci&3)*2 + ((ci>>2)&1)
// -> every fragment operand is one LDS.64, conflict-free.
// tap -> (parity, row offset): k0:(odd,0) k1:(even,0) k2:(odd,1)
//                              k3:(even,1) k4:(odd,2)
// Mainloop nest is tap -> h -> j so each accumulator's RAW distance is 16
// mmas (>= HMMA latency); accumulation order per acc is unchanged.
// ---------------------------------------------------------------------------

typedef unsigned int       u32;
typedef unsigned long long ull;

__device__ float g_a1[(size_t)512 * 128 * 1024];
__device__ float g_feat[2][512][256];
// tf32 conv1 weights, interleaved cols: [net][chunk 4][tap 5][co 128][pos 16]
__device__ __align__(16) float g_w1tf[2][4][5][128][16];
// tf32 conv2 weights: [net][coh 2][chunk 8][tap 5][co 128][pos 16]
__device__ __align__(16) float g_w2tf[2][2][8][5][128][16];

// ---------------- helpers ---------------------------------------------------
__device__ __forceinline__ u32 to_tf32(float v) {
    u32 r;
    asm("cvt.rna.tf32.f32 %0, %1;" : "=r"(r) : "f"(v));
    return r;
}
__device__ __forceinline__ void mma_tf32(float* d, const u32* a, u32 b0, u32 b1) {
    asm volatile(
        "mma.sync.aligned.m16n8k8.row.col.f32.tf32.tf32.f32 "
        "{%0,%1,%2,%3}, {%4,%5,%6,%7}, {%8,%9}, {%0,%1,%2,%3};"
        : "+f"(d[0]), "+f"(d[1]), "+f"(d[2]), "+f"(d[3])
        : "r"(a[0]), "r"(a[1]), "r"(a[2]), "r"(a[3]), "r"(b0), "r"(b1));
}
__device__ __forceinline__ u32 smem_u32(const void* p) {
    u32 a;
    asm("{ .reg .u64 t; cvta.to.shared.u64 t, %1; cvt.u32.u64 %0, t; }"
        : "=r"(a) : "l"(p));
    return a;
}
__device__ __forceinline__ void cp16(u32 dst, const void* src) {
    asm volatile("cp.async.cg.shared.global [%0], [%1], 16;" :: "r"(dst), "l"(src));
}
#define CP_COMMIT() asm volatile("cp.async.commit_group;" ::: "memory")
#define CP_WAIT0()  asm volatile("cp.async.wait_group 0;" ::: "memory")

__host__ __device__ constexpr int posi(int ci) {
    return ((ci >> 3) << 3) + ((ci & 3) << 1) + ((ci >> 2) & 1);
}

#define PITCH 24
#define A_FLTS (5 * 128 * PITCH)   // 15360
#define B_FLTS (132 * PITCH)       // 3168

// ---------------------------------------------------------------------------
// prep kernels: tf32-round + column-interleave weights into per-(chunk,tap)
// contiguous tiles.
// ---------------------------------------------------------------------------
__global__ __launch_bounds__(256)
void prep_w1_kernel(const float* __restrict__ w_n0, const float* __restrict__ w_n1)
{
    int idx = blockIdx.x * 256 + threadIdx.x;
    const int total = 2 * 4 * 5 * 128 * 16;
    if (idx >= total) return;
    int r = idx;
    int ci = r & 15;   r >>= 4;
    int co = r & 127;  r >>= 7;
    int tap = r % 5;   r /= 5;
    int chunk = r & 3; r >>= 2;
    int net = r;
    const float* w = net ? w_n1 : w_n0;
    float v = w[(size_t)co * 320 + (chunk * 16 + ci) * 5 + tap];
    g_w1tf[net][chunk][tap][co][posi(ci)] = __uint_as_float(to_tf32(v));
}

__global__ __launch_bounds__(256)
void prep_w2_kernel(const float* __restrict__ w_n0, const float* __restrict__ w_n1)
{
    int idx = blockIdx.x * 256 + threadIdx.x;
    const int total = 2 * 2 * 8 * 5 * 128 * 16;
    if (idx >= total) return;
    int r = idx;
    int ci = r & 15;   r >>= 4;
    int co = r & 127;  r >>= 7;
    int tap = r % 5;   r /= 5;
    int chunk = r & 7; r >>= 3;
    int coh = r & 1;   r >>= 1;
    int net = r;
    const float* w = net ? w_n1 : w_n0;
    float v = w[(size_t)(coh * 128 + co) * 640 + (chunk * 16 + ci) * 5 + tap];
    g_w2tf[net][coh][chunk][tap][co][posi(ci)] = __uint_as_float(to_tf32(v));
}

// ---------------------------------------------------------------------------
// shared mainloop: tap -> h -> j; RAW distance per acc = 16 mmas.
// Accumulation order per acc (tap-major, h0 then h1) identical to before.
// ---------------------------------------------------------------------------
#define MMA_MAINLOOP(As, Be, Bo)                                               \
    _Pragma("unroll")                                                          \
    for (int tap = 0; tap < 5; tap++) {                                        \
        const float* Bb = (tap == 1 || tap == 3) ? (Be) : (Bo);                \
        const int roff = (tap < 2) ? 0 : ((tap == 4) ? 2 : 1);                 \
        u32 a[2][2][4];                                                        \
        _Pragma("unroll")                                                      \
        for (int m = 0; m < 2; m++) {                                          \
            const float* ab = (As) + (tap * 128 + wco + m * 16 + lr) * PITCH + 2 * lc; \
            _Pragma("unroll")                                                  \
            for (int h = 0; h < 2; h++) {                                      \
                float2 q0 = *(const float2*)&ab[8 * h];                        \
                float2 q1 = *(const float2*)&ab[8 * PITCH + 8 * h];            \
                a[m][h][0] = __float_as_uint(q0.x);                            \
                a[m][h][1] = __float_as_uint(q1.x);                            \
                a[m][h][2] = __float_as_uint(q0.y);                            \
                a[m][h][3] = __float_as_uint(q1.y);                            \
            }                                                                  \
        }                                                                      \
        const float* brow = Bb + (wt + lr + roff) * PITCH + 2 * lc;            \
        _Pragma("unroll")                                                      \
        for (int h = 0; h < 2; h++) {                                          \
            _Pragma("unroll")                                                  \
            for (int j = 0; j < 8; j++) {                                      \
                float2 p = *(const float2*)&brow[j * 8 * PITCH + 8 * h];       \
                u32 pb0 = __float_as_uint(p.x), pb1 = __float_as_uint(p.y);    \
                mma_tf32(acc[0][j], a[0][h], pb0, pb1);                        \
                mma_tf32(acc[1][j], a[1][h], pb0, pb1);                        \
            }                                                                  \
        }                                                                      \
    }

// ---------------------------------------------------------------------------
// conv01 via tf32 warp-MMA; conv0 computed on the fly into B tiles.
// grid (512 b, 8 t-tiles), 256 threads (8 warps). CTA 128co x 128t.
// ---------------------------------------------------------------------------
#define O1_BE  A_FLTS
#define O1_BO  (O1_BE + B_FLTS)
#define O1_X   (O1_BO + B_FLTS)
#define O1_W0  (O1_X + 1048)
#define O1_B0  (O1_W0 + 768)
#define C1_SMEM ((O1_B0 + 64) * 4)     // 94,304 bytes

__global__ __launch_bounds__(256, 2)
void conv01_mma_kernel(const float* __restrict__ x,
                       const float* __restrict__ w0,  // [64,2,5]
                       const float* __restrict__ b0,  // [64]
                       const float* __restrict__ b1,  // [128]
                       float* __restrict__ out,       // [512,128,1024]
                       int net)
{
    extern __shared__ float sm[];
    float* As  = sm;
    float* Be  = sm + O1_BE;
    float* Bo  = sm + O1_BO;
    float* xs0 = sm + O1_X;
    float* w0s = sm + O1_W0;   // padded [64][12]
    float* b0s = sm + O1_B0;

    const int tid  = threadIdx.x;
    const int lane = tid & 31;
    const int wid  = tid >> 5;
    const int b    = blockIdx.x;
    const int tt0  = blockIdx.y * 128;

    const int wco = (wid & 3) * 32;
    const int wt  = (wid >> 2) * 64;
    const int lr  = lane >> 2;
    const int lc  = lane & 3;
    const u32 uAs = smem_u32(As);

    // one-time CTA loads (division-free)
    for (int i = tid; i < 640; i += 256)
        w0s[(i / 10) * 12 + (i % 10)] = w0[i];
    if (tid < 64) b0s[tid] = b0[tid];
    {
        const int x0 = 4 * tt0 - 3;
        const float* xb = x + (size_t)b * 2 * 4096;
#pragma unroll
        for (int row = 0; row < 2; row++)
            for (int col = tid; col < 524; col += 256) {
                int gx = x0 + col;
                xs0[row * 524 + col] =
                    (gx >= 0 && gx < 4096) ? xb[(size_t)row * 4096 + gx] : 0.0f;
            }
    }

    float acc[2][8][4];
#pragma unroll
    for (int m = 0; m < 2; m++)
#pragma unroll
        for (int j = 0; j < 8; j++)
#pragma unroll
            for (int e = 0; e < 4; e++) acc[m][j][e] = 0.0f;

    __syncthreads();

    for (int chunk = 0; chunk < 4; chunk++) {
        const int ci0 = chunk * 16;

        // ---- A stage: cp.async of prep'd tile (packed 16 -> pitch 24) ----
        {
            const char* src = (const char*)&g_w1tf[net][chunk][0][0][0];
#pragma unroll
            for (int r = 0; r < 10; r++) {
                int i = r * 256 + tid;
                int row = i >> 2, seg = i & 3;
                cp16(uAs + (u32)(row * PITCH + seg * 4) * 4, src + (size_t)i * 16);
            }
            CP_COMMIT();
        }

        // ---- B stage: one t-row per thread; x taps in regs; broadcast w ----
        for (int r = tid; r < 259; r += 256) {
            int tau, cb;
            float* dst;
            if (r < 129) {               // even rows: Be[r] = a0(2*tt0 + 2r)
                tau = 2 * tt0 + 2 * r;
                cb  = 4 * r + 2;
                dst = &Be[r * PITCH];
            } else {                     // odd rows: Bo[mm] = a0(2*tt0 + 2mm - 1)
                int mm = r - 129;
                tau = 2 * tt0 + 2 * mm - 1;
                cb  = 4 * mm;
                dst = &Bo[mm * PITCH];
            }
            u32 v[16];
            if (tau >= 0 && tau < 2048) {
                float xv[10];
#pragma unroll
                for (int k = 0; k < 5; k++) xv[k] = xs0[cb + k];
#pragma unroll
                for (int k = 0; k < 5; k++) xv[5 + k] = xs0[524 + cb + k];
#pragma unroll
                for (int ci = 0; ci < 16; ci++) {
                    const float* wc = &w0s[(ci0 + ci) * 12];
                    float4 wA = *(const float4*)wc;
                    float4 wB = *(const float4*)(wc + 4);
                    float2 wC = *(const float2*)(wc + 8);
                    float a = b0s[ci0 + ci];
                    a = fmaf(wA.x, xv[0], a); a = fmaf(wA.y, xv[1], a);
                    a = fmaf(wA.z, xv[2], a); a = fmaf(wA.w, xv[3], a);
                    a = fmaf(wB.x, xv[4], a); a = fmaf(wB.y, xv[5], a);
                    a = fmaf(wB.z, xv[6], a); a = fmaf(wB.w, xv[7], a);
                    a = fmaf(wC.x, xv[8], a); a = fmaf(wC.y, xv[9], a);
                    v[posi(ci)] = to_tf32(fmaxf(a, 0.0f));
                }
            } else {
#pragma unroll
                for (int i = 0; i < 16; i++) v[i] = 0u;
            }
#pragma unroll
            for (int s = 0; s < 4; s++)
                *(float4*)&dst[4 * s] = make_float4(
                    __uint_as_float(v[4 * s]),     __uint_as_float(v[4 * s + 1]),
                    __uint_as_float(v[4 * s + 2]), __uint_as_float(v[4 * s + 3]));
        }
        CP_WAIT0();
        __syncthreads();

        MMA_MAINLOOP(As, Be, Bo)
        __syncthreads();
    }

    // ---- epilogue: bias+relu, write a1; t = wt + j*8 + 2lc (+1) ----
#pragma unroll
    for (int m = 0; m < 2; m++) {
        int co_a = wco + m * 16 + lr;
        int co_b = co_a + 8;
        float bva = b1[co_a];
        float bvb = b1[co_b];
        float* oa = out + ((size_t)b * 128 + co_a) * 1024 + tt0;
        float* ob = out + ((size_t)b * 128 + co_b) * 1024 + tt0;
#pragma unroll
        for (int j = 0; j < 8; j++) {
            int t = wt + j * 8 + 2 * lc;
            *(float2*)&oa[t] = make_float2(fmaxf(acc[m][j][0] + bva, 0.0f),
                                           fmaxf(acc[m][j][1] + bva, 0.0f));
            *(float2*)&ob[t] = make_float2(fmaxf(acc[m][j][2] + bvb, 0.0f),
                                           fmaxf(acc[m][j][3] + bvb, 0.0f));
        }
    }
}

// ---------------------------------------------------------------------------
// conv2 via tf32 warp-MMA + fused pool. grid (512 b, 4 tq, 2 coh), 256 thr.
// ---------------------------------------------------------------------------
#define O2_BE  A_FLTS
#define O2_BO  (O2_BE + B_FLTS)
#define C2_SMEM ((O2_BO + B_FLTS) * 4)  // 86,784 bytes

__global__ __launch_bounds__(256, 2)
void conv2_mma_kernel(const float* __restrict__ in,    // [512,128,1024] fp32
                      const float* __restrict__ bias,  // [256]
                      float* __restrict__ feat,        // [512,256] sums
                      int net)
{
    extern __shared__ float sm[];
    float* As = sm;
    float* Be = sm + O2_BE;
    float* Bo = sm + O2_BO;

    const int tid  = threadIdx.x;
    const int lane = tid & 31;
    const int wid  = tid >> 5;
    const int b    = blockIdx.x;
    const int tt0  = blockIdx.y * 128;
    const int co0  = blockIdx.z * 128;

    const int wco = (wid & 3) * 32;
    const int wt  = (wid >> 2) * 64;
    const int lr  = lane >> 2;
    const int lc  = lane & 3;
    const u32 uAs = smem_u32(As);

    float acc[2][8][4];
#pragma unroll
    for (int m = 0; m < 2; m++)
#pragma unroll
        for (int j = 0; j < 8; j++)
#pragma unroll
            for (int e = 0; e < 4; e++) acc[m][j][e] = 0.0f;

    const float* inb = in + (size_t)b * 128 * 1024;
    const int bci  = tid >> 4;
    const int brl  = tid & 15;
    const int pcol = posi(bci);

    for (int chunk = 0; chunk < 8; chunk++) {
        const int ci0 = chunk * 16;
        // ---- A stage: cp.async ----
        {
            const char* src = (const char*)&g_w2tf[net][co0 >> 7][chunk][0][0][0];
#pragma unroll
            for (int r = 0; r < 10; r++) {
                int i = r * 256 + tid;
                int row = i >> 2, seg = i & 3;
                cp16(uAs + (u32)(row * PITCH + seg * 4) * 4, src + (size_t)i * 16);
            }
            CP_COMMIT();
        }
        // ---- B stage: parity-split copy + tf32 ----
        {
            const float* arow = inb + (size_t)(ci0 + bci) * 1024;
            for (int m = brl; m < 129; m += 16) {
                int g0 = 2 * tt0 + 2 * m;
                float ev = 0.0f, od = 0.0f;
                if (g0 < 1024) {
                    float2 v = *(const float2*)&arow[g0];
                    ev = v.x; od = v.y;
                }
                Be[m * PITCH + pcol]       = __uint_as_float(to_tf32(ev));
                Bo[(m + 1) * PITCH + pcol] = __uint_as_float(to_tf32(od));
            }
            if (tid < 16) {  // odd row 0: g = 2*tt0 - 1
                float v = (tt0 > 0) ? inb[(size_t)(ci0 + tid) * 1024 + 2 * tt0 - 1] : 0.0f;
                Bo[posi(tid)] = __uint_as_float(to_tf32(v));
            }
        }
        CP_WAIT0();
        __syncthreads();

        MMA_MAINLOOP(As, Be, Bo)
        __syncthreads();
    }

    // ---- epilogue: bias+relu, sum over t, quad-reduce, atomicAdd ----
    float* fb = feat + (size_t)b * 256;
#pragma unroll
    for (int m = 0; m < 2; m++) {
        int r0 = co0 + wco + m * 16 + lr;
        int r1 = r0 + 8;
        float bv0 = __ldg(&bias[r0]);
        float bv1 = __ldg(&bias[r1]);
        float s0 = 0.0f, s1 = 0.0f;
#pragma unroll
        for (int j = 0; j < 8; j++) {
            s0 += fmaxf(acc[m][j][0] + bv0, 0.0f) + fmaxf(acc[m][j][1] + bv0, 0.0f);
            s1 += fmaxf(acc[m][j][2] + bv1, 0.0f) + fmaxf(acc[m][j][3] + bv1, 0.0f);
        }
        s0 += __shfl_xor_sync(0xffffffffu, s0, 1);
        s0 += __shfl_xor_sync(0xffffffffu, s0, 2);
        s1 += __shfl_xor_sync(0xffffffffu, s1, 1);
        s1 += __shfl_xor_sync(0xffffffffu, s1, 2);
        if (lc == 0) {
            atomicAdd(&fb[r0], s0);
            atomicAdd(&fb[r1], s1);
        }
    }
}

// ---------------------------------------------------------------------------
__global__ void zero_feat_kernel()
{
    int i = blockIdx.x * 256 + threadIdx.x;
    if (i < 2 * 512 * 256) ((float*)g_feat)[i] = 0.0f;
}

// ---------------------------------------------------------------------------
// heads + softmax + hierarchical routing. 1 warp per sample.
// ---------------------------------------------------------------------------
__global__ __launch_bounds__(32)
void head_kernel(const float* __restrict__ wh1, const float* __restrict__ bh1,
                 const float* __restrict__ wh2, const float* __restrict__ bh2,
                 float* __restrict__ out)
{
    const int b = blockIdx.x;
    const int lane = threadIdx.x;
    const float* f1 = &g_feat[0][b][0];
    const float* f2 = &g_feat[1][b][0];
    const float inv_pool = 1.0f / 512.0f;

    float lg1[3], lg2[2];
#pragma unroll
    for (int cls = 0; cls < 3; cls++) {
        float s = 0.0f;
        for (int c = lane; c < 256; c += 32) s += f1[c] * wh1[cls * 256 + c];
#pragma unroll
        for (int off = 16; off > 0; off >>= 1) s += __shfl_xor_sync(0xffffffffu, s, off);
        lg1[cls] = s * inv_pool + bh1[cls];
    }
#pragma unroll
    for (int cls = 0; cls < 2; cls++) {
        float s = 0.0f;
        for (int c = lane; c < 256; c += 32) s += f2[c] * wh2[cls * 256 + c];
#pragma unroll
        for (int off = 16; off > 0; off >>= 1) s += __shfl_xor_sync(0xffffffffu, s, off);
        lg2[cls] = s * inv_pool + bh2[cls];
    }

    if (lane == 0) {
        float m = fmaxf(lg1[0], fmaxf(lg1[1], lg1[2]));
        float e0 = expf(lg1[0] - m), e1 = expf(lg1[1] - m), e2 = expf(lg1[2] - m);
        float inv = 1.0f / (e0 + e1 + e2);
        float p0 = e0 * inv, p1 = e1 * inv, p2 = e2 * inv;
        int pred = 0; float best = p0;
        if (p1 > best) { best = p1; pred = 1; }
        if (p2 > best) { best = p2; pred = 2; }

        float m2 = fmaxf(lg2[0], lg2[1]);
        float q0 = expf(lg2[0] - m2), q1 = expf(lg2[1] - m2);
        float inv2 = 1.0f / (q0 + q1);
        q0 *= inv2; q1 *= inv2;

        out[b * 4 + 0] = (pred == 0) ? p0 : 0.0f;
        out[b * 4 + 1] = (pred == 1) ? p1 : 0.0f;
        out[b * 4 + 2] = (pred == 2) ? q0 : 0.0f;
        out[b * 4 + 3] = (pred == 2) ? q1 : 0.0f;
    }
}

// ---------------------------------------------------------------------------
extern "C" void kernel_launch(void* const* d_in, const int* in_sizes, int n_in,
                              void* d_out, int out_size)
{
    (void)in_sizes; (void)n_in; (void)out_size;
    const float* x = (const float*)d_in[0];

    const float* W[2][8];
    for (int net = 0; net < 2; net++)
        for (int i = 0; i < 8; i++)
            W[net][i] = (const float*)d_in[1 + net * 8 + i];

    float* out = (float*)d_out;

    float *a1, *feat;
    cudaGetSymbolAddress((void**)&a1, g_a1);
    cudaGetSymbolAddress((void**)&feat, g_feat);

    cudaFuncSetAttribute(conv01_mma_kernel,
                         cudaFuncAttributeMaxDynamicSharedMemorySize, C1_SMEM);
    cudaFuncSetAttribute(conv2_mma_kernel,
                         cudaFuncAttributeMaxDynamicSharedMemorySize, C2_SMEM);

    zero_feat_kernel<<<1024, 256>>>();
    prep_w1_kernel<<<320, 256>>>(W[0][2], W[1][2]);
    prep_w2_kernel<<<1280, 256>>>(W[0][4], W[1][4]);

    for (int net = 0; net < 2; net++) {
        conv01_mma_kernel<<<dim3(512, 8), 256, C1_SMEM>>>(
            x, W[net][0], W[net][1], W[net][3], a1, net);
        conv2_mma_kernel<<<dim3(512, 4, 2), 256, C2_SMEM>>>(
            a1, W[net][5], feat + (size_t)net * 512 * 256, net);
    }

    head_kernel<<<512, 32>>>(W[0][6], W[0][7], W[1][6], W[1][7], out);
}

// round 12
// speedup vs baseline: 3.9481x; 1.0011x over previous
#include <cuda_runtime.h>
#include <math.h>

// ---------------------------------------------------------------------------
// HierarchicalCNN: two 3-layer strided conv1d nets + pooled heads + routing.
// Both conv stages on tf32 mma.sync m16n8k8 (single pass, rna).
//
// Smem layout for MMA tiles: column-interleaved, pitch 24 floats.
//   pos(ci) = (ci>>3)*8 + (ci&3)*2 + ((ci>>2)&1)
// -> every fragment operand is one LDS.64 at the 2-wavefront floor.
// tap -> (parity, row offset): k0:(odd,0) k1:(even,0) k2:(odd,1)
//                              k3:(even,1) k4:(odd,2)
// Mainloop: per (tap,h) ALL 8 B fragments are loaded into registers first,
// then the 16 dependent mmas issue as a burst -> LDS latency amortized once
// per batch instead of per fragment. Accumulation order per acc unchanged.
// ---------------------------------------------------------------------------

typedef unsigned int       u32;
typedef unsigned long long ull;

__device__ float g_a1[(size_t)512 * 128 * 1024];
__device__ float g_feat[2][512][256];
// tf32 conv1 weights, interleaved cols: [net][chunk 4][tap 5][co 128][pos 16]
__device__ __align__(16) float g_w1tf[2][4][5][128][16];
// tf32 conv2 weights: [net][coh 2][chunk 8][tap 5][co 128][pos 16]
__device__ __align__(16) float g_w2tf[2][2][8][5][128][16];

// ---------------- helpers ---------------------------------------------------
__device__ __forceinline__ u32 to_tf32(float v) {
    u32 r;
    asm("cvt.rna.tf32.f32 %0, %1;" : "=r"(r) : "f"(v));
    return r;
}
__device__ __forceinline__ void mma_tf32(float* d, const u32* a, u32 b0, u32 b1) {
    asm volatile(
        "mma.sync.aligned.m16n8k8.row.col.f32.tf32.tf32.f32 "
        "{%0,%1,%2,%3}, {%4,%5,%6,%7}, {%8,%9}, {%0,%1,%2,%3};"
        : "+f"(d[0]), "+f"(d[1]), "+f"(d[2]), "+f"(d[3])
        : "r"(a[0]), "r"(a[1]), "r"(a[2]), "r"(a[3]), "r"(b0), "r"(b1));
}
__device__ __forceinline__ u32 smem_u32(const void* p) {
    u32 a;
    asm("{ .reg .u64 t; cvta.to.shared.u64 t, %1; cvt.u32.u64 %0, t; }"
        : "=r"(a) : "l"(p));
    return a;
}
__device__ __forceinline__ void cp16(u32 dst, const void* src) {
    asm volatile("cp.async.cg.shared.global [%0], [%1], 16;" :: "r"(dst), "l"(src));
}
#define CP_COMMIT() asm volatile("cp.async.commit_group;" ::: "memory")
#define CP_WAIT0()  asm volatile("cp.async.wait_group 0;" ::: "memory")

__host__ __device__ constexpr int posi(int ci) {
    return ((ci >> 3) << 3) + ((ci & 3) << 1) + ((ci >> 2) & 1);
}

#define PITCH 24
#define A_FLTS (5 * 128 * PITCH)   // 15360
#define B_FLTS (132 * PITCH)       // 3168

// ---------------------------------------------------------------------------
// prep kernels
// ---------------------------------------------------------------------------
__global__ __launch_bounds__(256)
void prep_w1_kernel(const float* __restrict__ w_n0, const float* __restrict__ w_n1)
{
    int idx = blockIdx.x * 256 + threadIdx.x;
    const int total = 2 * 4 * 5 * 128 * 16;
    if (idx >= total) return;
    int r = idx;
    int ci = r & 15;   r >>= 4;
    int co = r & 127;  r >>= 7;
    int tap = r % 5;   r /= 5;
    int chunk = r & 3; r >>= 2;
    int net = r;
    const float* w = net ? w_n1 : w_n0;
    float v = w[(size_t)co * 320 + (chunk * 16 + ci) * 5 + tap];
    g_w1tf[net][chunk][tap][co][posi(ci)] = __uint_as_float(to_tf32(v));
}

__global__ __launch_bounds__(256)
void prep_w2_kernel(const float* __restrict__ w_n0, const float* __restrict__ w_n1)
{
    int idx = blockIdx.x * 256 + threadIdx.x;
    const int total = 2 * 2 * 8 * 5 * 128 * 16;
    if (idx >= total) return;
    int r = idx;
    int ci = r & 15;   r >>= 4;
    int co = r & 127;  r >>= 7;
    int tap = r % 5;   r /= 5;
    int chunk = r & 7; r >>= 3;
    int coh = r & 1;   r >>= 1;
    int net = r;
    const float* w = net ? w_n1 : w_n0;
    float v = w[(size_t)(coh * 128 + co) * 640 + (chunk * 16 + ci) * 5 + tap];
    g_w2tf[net][coh][chunk][tap][co][posi(ci)] = __uint_as_float(to_tf32(v));
}

// ---------------------------------------------------------------------------
// shared mainloop: per (tap,h) batch-load 8 B fragments, then 16 mmas.
// Accumulation order per acc (tap-major, h0 then h1) identical to before.
// ---------------------------------------------------------------------------
#define MMA_MAINLOOP(As, Be, Bo)                                               \
    _Pragma("unroll")                                                          \
    for (int tap = 0; tap < 5; tap++) {                                        \
        const float* Bb = (tap == 1 || tap == 3) ? (Be) : (Bo);                \
        const int roff = (tap < 2) ? 0 : ((tap == 4) ? 2 : 1);                 \
        u32 a[2][2][4];                                                        \
        _Pragma("unroll")                                                      \
        for (int m = 0; m < 2; m++) {                                          \
            const float* ab = (As) + (tap * 128 + wco + m * 16 + lr) * PITCH + 2 * lc; \
            _Pragma("unroll")                                                  \
            for (int h = 0; h < 2; h++) {                                      \
                float2 q0 = *(const float2*)&ab[8 * h];                        \
                float2 q1 = *(const float2*)&ab[8 * PITCH + 8 * h];            \
                a[m][h][0] = __float_as_uint(q0.x);                            \
                a[m][h][1] = __float_as_uint(q1.x);                            \
                a[m][h][2] = __float_as_uint(q0.y);                            \
                a[m][h][3] = __float_as_uint(q1.y);                            \
            }                                                                  \
        }                                                                      \
        const float* brow = Bb + (wt + lr + roff) * PITCH + 2 * lc;            \
        _Pragma("unroll")                                                      \
        for (int h = 0; h < 2; h++) {                                          \
            float2 p[8];                                                       \
            _Pragma("unroll")                                                  \
            for (int j = 0; j < 8; j++)                                        \
                p[j] = *(const float2*)&brow[j * 8 * PITCH + 8 * h];           \
            _Pragma("unroll")                                                  \
            for (int j = 0; j < 8; j++) {                                      \
                u32 pb0 = __float_as_uint(p[j].x);                             \
                u32 pb1 = __float_as_uint(p[j].y);                             \
                mma_tf32(acc[0][j], a[0][h], pb0, pb1);                        \
                mma_tf32(acc[1][j], a[1][h], pb0, pb1);                        \
            }                                                                  \
        }                                                                      \
    }

// ---------------------------------------------------------------------------
// conv01 via tf32 warp-MMA; conv0 computed on the fly into B tiles.
// grid (512 b, 8 t-tiles), 256 threads (8 warps). CTA 128co x 128t.
// ---------------------------------------------------------------------------
#define O1_BE  A_FLTS
#define O1_BO  (O1_BE + B_FLTS)
#define O1_X   (O1_BO + B_FLTS)
#define O1_W0  (O1_X + 1048)
#define O1_B0  (O1_W0 + 768)
#define C1_SMEM ((O1_B0 + 64) * 4)     // 94,304 bytes

__global__ __launch_bounds__(256, 2)
void conv01_mma_kernel(const float* __restrict__ x,
                       const float* __restrict__ w0,  // [64,2,5]
                       const float* __restrict__ b0,  // [64]
                       const float* __restrict__ b1,  // [128]
                       float* __restrict__ out,       // [512,128,1024]
                       int net)
{
    extern __shared__ float sm[];
    float* As  = sm;
    float* Be  = sm + O1_BE;
    float* Bo  = sm + O1_BO;
    float* xs0 = sm + O1_X;
    float* w0s = sm + O1_W0;   // padded [64][12]
    float* b0s = sm + O1_B0;

    const int tid  = threadIdx.x;
    const int lane = tid & 31;
    const int wid  = tid >> 5;
    const int b    = blockIdx.x;
    const int tt0  = blockIdx.y * 128;

    const int wco = (wid & 3) * 32;
    const int wt  = (wid >> 2) * 64;
    const int lr  = lane >> 2;
    const int lc  = lane & 3;
    const u32 uAs = smem_u32(As);

    // one-time CTA loads
    for (int i = tid; i < 640; i += 256)
        w0s[(i / 10) * 12 + (i % 10)] = w0[i];
    if (tid < 64) b0s[tid] = b0[tid];
    {
        const int x0 = 4 * tt0 - 3;
        const float* xb = x + (size_t)b * 2 * 4096;
#pragma unroll
        for (int row = 0; row < 2; row++)
            for (int col = tid; col < 524; col += 256) {
                int gx = x0 + col;
                xs0[row * 524 + col] =
                    (gx >= 0 && gx < 4096) ? xb[(size_t)row * 4096 + gx] : 0.0f;
            }
    }

    float acc[2][8][4];
#pragma unroll
    for (int m = 0; m < 2; m++)
#pragma unroll
        for (int j = 0; j < 8; j++)
#pragma unroll
            for (int e = 0; e < 4; e++) acc[m][j][e] = 0.0f;

    __syncthreads();

    for (int chunk = 0; chunk < 4; chunk++) {
        const int ci0 = chunk * 16;

        // ---- A stage: cp.async of prep'd tile (packed 16 -> pitch 24) ----
        {
            const char* src = (const char*)&g_w1tf[net][chunk][0][0][0];
#pragma unroll
            for (int r = 0; r < 10; r++) {
                int i = r * 256 + tid;
                int row = i >> 2, seg = i & 3;
                cp16(uAs + (u32)(row * PITCH + seg * 4) * 4, src + (size_t)i * 16);
            }
            CP_COMMIT();
        }

        // ---- B stage: one t-row per thread; x taps in regs; broadcast w ----
        for (int r = tid; r < 259; r += 256) {
            int tau, cb;
            float* dst;
            if (r < 129) {               // even rows: Be[r] = a0(2*tt0 + 2r)
                tau = 2 * tt0 + 2 * r;
                cb  = 4 * r + 2;
                dst = &Be[r * PITCH];
            } else {                     // odd rows: Bo[mm] = a0(2*tt0 + 2mm - 1)
                int mm = r - 129;
                tau = 2 * tt0 + 2 * mm - 1;
                cb  = 4 * mm;
                dst = &Bo[mm * PITCH];
            }
            u32 v[16];
            if (tau >= 0 && tau < 2048) {
                float xv[10];
#pragma unroll
                for (int k = 0; k < 5; k++) xv[k] = xs0[cb + k];
#pragma unroll
                for (int k = 0; k < 5; k++) xv[5 + k] = xs0[524 + cb + k];
#pragma unroll
                for (int ci = 0; ci < 16; ci++) {
                    const float* wc = &w0s[(ci0 + ci) * 12];
                    float4 wA = *(const float4*)wc;
                    float4 wB = *(const float4*)(wc + 4);
                    float2 wC = *(const float2*)(wc + 8);
                    float a = b0s[ci0 + ci];
                    a = fmaf(wA.x, xv[0], a); a = fmaf(wA.y, xv[1], a);
                    a = fmaf(wA.z, xv[2], a); a = fmaf(wA.w, xv[3], a);
                    a = fmaf(wB.x, xv[4], a); a = fmaf(wB.y, xv[5], a);
                    a = fmaf(wB.z, xv[6], a); a = fmaf(wB.w, xv[7], a);
                    a = fmaf(wC.x, xv[8], a); a = fmaf(wC.y, xv[9], a);
                    v[posi(ci)] = to_tf32(fmaxf(a, 0.0f));
                }
            } else {
#pragma unroll
                for (int i = 0; i < 16; i++) v[i] = 0u;
            }
#pragma unroll
            for (int s = 0; s < 4; s++)
                *(float4*)&dst[4 * s] = make_float4(
                    __uint_as_float(v[4 * s]),     __uint_as_float(v[4 * s + 1]),
                    __uint_as_float(v[4 * s + 2]), __uint_as_float(v[4 * s + 3]));
        }
        CP_WAIT0();
        __syncthreads();

        MMA_MAINLOOP(As, Be, Bo)
        __syncthreads();
    }

    // ---- epilogue: bias+relu, write a1; t = wt + j*8 + 2lc (+1) ----
#pragma unroll
    for (int m = 0; m < 2; m++) {
        int co_a = wco + m * 16 + lr;
        int co_b = co_a + 8;
        float bva = b1[co_a];
        float bvb = b1[co_b];
        float* oa = out + ((size_t)b * 128 + co_a) * 1024 + tt0;
        float* ob = out + ((size_t)b * 128 + co_b) * 1024 + tt0;
#pragma unroll
        for (int j = 0; j < 8; j++) {
            int t = wt + j * 8 + 2 * lc;
            *(float2*)&oa[t] = make_float2(fmaxf(acc[m][j][0] + bva, 0.0f),
                                           fmaxf(acc[m][j][1] + bva, 0.0f));
            *(float2*)&ob[t] = make_float2(fmaxf(acc[m][j][2] + bvb, 0.0f),
                                           fmaxf(acc[m][j][3] + bvb, 0.0f));
        }
    }
}

// ---------------------------------------------------------------------------
// conv2 via tf32 warp-MMA + fused pool. grid (512 b, 4 tq, 2 coh), 256 thr.
// ---------------------------------------------------------------------------
#define O2_BE  A_FLTS
#define O2_BO  (O2_BE + B_FLTS)
#define C2_SMEM ((O2_BO + B_FLTS) * 4)  // 86,784 bytes

__global__ __launch_bounds__(256, 2)
void conv2_mma_kernel(const float* __restrict__ in,    // [512,128,1024] fp32
                      const float* __restrict__ bias,  // [256]
                      float* __restrict__ feat,        // [512,256] sums
                      int net)
{
    extern __shared__ float sm[];
    float* As = sm;
    float* Be = sm + O2_BE;
    float* Bo = sm + O2_BO;

    const int tid  = threadIdx.x;
    const int lane = tid & 31;
    const int wid  = tid >> 5;
    const int b    = blockIdx.x;
    const int tt0  = blockIdx.y * 128;
    const int co0  = blockIdx.z * 128;

    const int wco = (wid & 3) * 32;
    const int wt  = (wid >> 2) * 64;
    const int lr  = lane >> 2;
    const int lc  = lane & 3;
    const u32 uAs = smem_u32(As);

    float acc[2][8][4];
#pragma unroll
    for (int m = 0; m < 2; m++)
#pragma unroll
        for (int j = 0; j < 8; j++)
#pragma unroll
            for (int e = 0; e < 4; e++) acc[m][j][e] = 0.0f;

    const float* inb = in + (size_t)b * 128 * 1024;
    const int bci  = tid >> 4;
    const int brl  = tid & 15;
    const int pcol = posi(bci);

    for (int chunk = 0; chunk < 8; chunk++) {
        const int ci0 = chunk * 16;
        // ---- A stage: cp.async ----
        {
            const char* src = (const char*)&g_w2tf[net][co0 >> 7][chunk][0][0][0];
#pragma unroll
            for (int r = 0; r < 10; r++) {
                int i = r * 256 + tid;
                int row = i >> 2, seg = i & 3;
                cp16(uAs + (u32)(row * PITCH + seg * 4) * 4, src + (size_t)i * 16);
            }
            CP_COMMIT();
        }
        // ---- B stage: parity-split copy + tf32 ----
        {
            const float* arow = inb + (size_t)(ci0 + bci) * 1024;
            for (int m = brl; m < 129; m += 16) {
                int g0 = 2 * tt0 + 2 * m;
                float ev = 0.0f, od = 0.0f;
                if (g0 < 1024) {
                    float2 v = *(const float2*)&arow[g0];
                    ev = v.x; od = v.y;
                }
                Be[m * PITCH + pcol]       = __uint_as_float(to_tf32(ev));
                Bo[(m + 1) * PITCH + pcol] = __uint_as_float(to_tf32(od));
            }
            if (tid < 16) {  // odd row 0: g = 2*tt0 - 1
                float v = (tt0 > 0) ? inb[(size_t)(ci0 + tid) * 1024 + 2 * tt0 - 1] : 0.0f;
                Bo[posi(tid)] = __uint_as_float(to_tf32(v));
            }
        }
        CP_WAIT0();
        __syncthreads();

        MMA_MAINLOOP(As, Be, Bo)
        __syncthreads();
    }

    // ---- epilogue: bias+relu, sum over t, quad-reduce, atomicAdd ----
    float* fb = feat + (size_t)b * 256;
#pragma unroll
    for (int m = 0; m < 2; m++) {
        int r0 = co0 + wco + m * 16 + lr;
        int r1 = r0 + 8;
        float bv0 = __ldg(&bias[r0]);
        float bv1 = __ldg(&bias[r1]);
        float s0 = 0.0f, s1 = 0.0f;
#pragma unroll
        for (int j = 0; j < 8; j++) {
            s0 += fmaxf(acc[m][j][0] + bv0, 0.0f) + fmaxf(acc[m][j][1] + bv0, 0.0f);
            s1 += fmaxf(acc[m][j][2] + bv1, 0.0f) + fmaxf(acc[m][j][3] + bv1, 0.0f);
        }
        s0 += __shfl_xor_sync(0xffffffffu, s0, 1);
        s0 += __shfl_xor_sync(0xffffffffu, s0, 2);
        s1 += __shfl_xor_sync(0xffffffffu, s1, 1);
        s1 += __shfl_xor_sync(0xffffffffu, s1, 2);
        if (lc == 0) {
            atomicAdd(&fb[r0], s0);
            atomicAdd(&fb[r1], s1);
        }
    }
}

// ---------------------------------------------------------------------------
__global__ void zero_feat_kernel()
{
    int i = blockIdx.x * 256 + threadIdx.x;
    if (i < 2 * 512 * 256) ((float*)g_feat)[i] = 0.0f;
}

// ---------------------------------------------------------------------------
// heads + softmax + hierarchical routing. 1 warp per sample.
// ---------------------------------------------------------------------------
__global__ __launch_bounds__(32)
void head_kernel(const float* __restrict__ wh1, const float* __restrict__ bh1,
                 const float* __restrict__ wh2, const float* __restrict__ bh2,
                 float* __restrict__ out)
{
    const int b = blockIdx.x;
    const int lane = threadIdx.x;
    const float* f1 = &g_feat[0][b][0];
    const float* f2 = &g_feat[1][b][0];
    const float inv_pool = 1.0f / 512.0f;

    float lg1[3], lg2[2];
#pragma unroll
    for (int cls = 0; cls < 3; cls++) {
        float s = 0.0f;
        for (int c = lane; c < 256; c += 32) s += f1[c] * wh1[cls * 256 + c];
#pragma unroll
        for (int off = 16; off > 0; off >>= 1) s += __shfl_xor_sync(0xffffffffu, s, off);
        lg1[cls] = s * inv_pool + bh1[cls];
    }
#pragma unroll
    for (int cls = 0; cls < 2; cls++) {
        float s = 0.0f;
        for (int c = lane; c < 256; c += 32) s += f2[c] * wh2[cls * 256 + c];
#pragma unroll
        for (int off = 16; off > 0; off >>= 1) s += __shfl_xor_sync(0xffffffffu, s, off);
        lg2[cls] = s * inv_pool + bh2[cls];
    }

    if (lane == 0) {
        float m = fmaxf(lg1[0], fmaxf(lg1[1], lg1[2]));
        float e0 = expf(lg1[0] - m), e1 = expf(lg1[1] - m), e2 = expf(lg1[2] - m);
        float inv = 1.0f / (e0 + e1 + e2);
        float p0 = e0 * inv, p1 = e1 * inv, p2 = e2 * inv;
        int pred = 0; float best = p0;
        if (p1 > best) { best = p1; pred = 1; }
        if (p2 > best) { best = p2; pred = 2; }

        float m2 = fmaxf(lg2[0], lg2[1]);
        float q0 = expf(lg2[0] - m2), q1 = expf(lg2[1] - m2);
        float inv2 = 1.0f / (q0 + q1);
        q0 *= inv2; q1 *= inv2;

        out[b * 4 + 0] = (pred == 0) ? p0 : 0.0f;
        out[b * 4 + 1] = (pred == 1) ? p1 : 0.0f;
        out[b * 4 + 2] = (pred == 2) ? q0 : 0.0f;
        out[b * 4 + 3] = (pred == 2) ? q1 : 0.0f;
    }
}

// ---------------------------------------------------------------------------
extern "C" void kernel_launch(void* const* d_in, const int* in_sizes, int n_in,
                              void* d_out, int out_size)
{
    (void)in_sizes; (void)n_in; (void)out_size;
    const float* x = (const float*)d_in[0];

    const float* W[2][8];
    for (int net = 0; net < 2; net++)
        for (int i = 0; i < 8; i++)
            W[net][i] = (const float*)d_in[1 + net * 8 + i];

    float* out = (float*)d_out;

    float *a1, *feat;
    cudaGetSymbolAddress((void**)&a1, g_a1);
    cudaGetSymbolAddress((void**)&feat, g_feat);

    cudaFuncSetAttribute(conv01_mma_kernel,
                         cudaFuncAttributeMaxDynamicSharedMemorySize, C1_SMEM);
    cudaFuncSetAttribute(conv2_mma_kernel,
                         cudaFuncAttributeMaxDynamicSharedMemorySize, C2_SMEM);

    zero_feat_kernel<<<1024, 256>>>();
    prep_w1_kernel<<<320, 256>>>(W[0][2], W[1][2]);
    prep_w2_kernel<<<1280, 256>>>(W[0][4], W[1][4]);

    for (int net = 0; net < 2; net++) {
        conv01_mma_kernel<<<dim3(512, 8), 256, C1_SMEM>>>(
            x, W[net][0], W[net][1], W[net][3], a1, net);
        conv2_mma_kernel<<<dim3(512, 4, 2), 256, C2_SMEM>>>(
            a1, W[net][5], feat + (size_t)net * 512 * 256, net);
    }

    head_kernel<<<512, 32>>>(W[0][6], W[0][7], W[1][6], W[1][7], out);
}